// round 10
// baseline (speedup 1.0000x reference)
#include <cuda_runtime.h>
#include <cuda_bf16.h>
#include <cuda_fp16.h>
#include <mma.h>
#include <math.h>
#include <cstdint>

using namespace nvcuda;

#define N_NODES 100000
#define N_EDGES 1600000
#define N_PAD 100096                          // 782*128
#define NB_SCAN ((N_NODES + 1023) / 1024)     // 98

#define TS 136                                // smem A/W tile stride (bf16 elems)
#define T2S 88                                // smem W2 tile stride
#define TILE_ELEMS (128 * TS)

// gemm1 smem: AH, AL, WLH, WLL, WRH, WRL  (6 x 128 x 136 bf16)
#define GEMM1_SMEM (6 * TILE_ELEMS * 2)
// fused aggr+gemm2 smem: AH, AL (128x136 bf16) + W2H, W2L (128x88 bf16)
#define FUSED_SMEM ((2 * 128 * TS + 2 * 128 * T2S) * 2)

// -------- scratch (static __device__ globals; no runtime alloc) ----------
__device__ int    g_is64;
__device__ int    g_degi[N_NODES];
__device__ int    g_cursor[N_NODES];
__device__ int    g_rowstart[N_NODES + 1];
__device__ int    g_bsum[NB_SCAN];
__device__ int    g_boff[NB_SCAN];
__device__ int    g_csrc[N_EDGES];
__device__ __half g_y1h[(size_t)N_PAD * 128]; // x @ Wl1  (fp16 — gathered 16x per node)
__device__ float  g_yr[(size_t)N_PAD * 128];  // x @ Wr1  (fp32 — read once per node)
__device__ __half g_pqh[(size_t)N_PAD * 80];  // [p(40) | q(40)] per node (fp16)
// precomputed weight splits (bf16 hi/lo)
__device__ __nv_bfloat16 g_wl1h[16384], g_wl1l[16384];
__device__ __nv_bfloat16 g_wr1h[16384], g_wr1l[16384];
__device__ __nv_bfloat16 g_w2h[10240],  g_w2l[10240];   // [Wl2|Wr2] 128x80

// edge accessor: works for int32 or int64 edge_index
__device__ __forceinline__ int edge_at(const void* ei, long long idx) {
    if (g_is64) return (int)((const long long*)ei)[idx];
    return ((const int*)ei)[idx];
}

// -------------------- dtype detect + zero + weight prep --------------------
__global__ void k_detect(const int* __restrict__ ei32) {
    __shared__ int nz;
    if (threadIdx.x == 0) nz = 0;
    __syncthreads();
    if (ei32[2 * threadIdx.x + 1] != 0) atomicAdd(&nz, 1);
    __syncthreads();
    if (threadIdx.x == 0) g_is64 = (nz == 0) ? 1 : 0;
}

__global__ void k_zero2() {
    int i = blockIdx.x * blockDim.x + threadIdx.x;
    if (i < N_NODES) { g_degi[i] = 0; g_cursor[i] = 0; }
}

__device__ __forceinline__ void split1(float v, __nv_bfloat16& h, __nv_bfloat16& l) {
    h = __float2bfloat16_rn(v);
    l = __float2bfloat16_rn(v - __bfloat162float(h));
}

__global__ __launch_bounds__(1024) void k_prep_w(
    const float* __restrict__ Wl1, const float* __restrict__ Wr1,
    const float* __restrict__ Wl2, const float* __restrict__ Wr2) {
    for (int i = threadIdx.x; i < 16384; i += 1024) {
        split1(Wl1[i], g_wl1h[i], g_wl1l[i]);
        split1(Wr1[i], g_wr1h[i], g_wr1l[i]);
    }
    for (int i = threadIdx.x; i < 10240; i += 1024) {
        int k = i / 80, j = i % 80;
        float v = (j < 40) ? Wl2[k * 40 + j] : Wr2[k * 40 + (j - 40)];
        split1(v, g_w2h[i], g_w2l[i]);
    }
}

// -------------------- CSR build --------------------

__global__ void k_count(const void* __restrict__ ei) {
    for (int e = blockIdx.x * blockDim.x + threadIdx.x; e < N_EDGES;
         e += gridDim.x * blockDim.x) {
        int d = edge_at(ei, (long long)N_EDGES + e);
        atomicAdd(&g_degi[d], 1);
    }
}

__global__ __launch_bounds__(1024) void k_scan1() {
    __shared__ int wsum[32];
    int i = blockIdx.x * 1024 + threadIdx.x;
    int lane = threadIdx.x & 31, wid = threadIdx.x >> 5;
    int v = (i < N_NODES) ? g_degi[i] : 0;
    int pre = v;
#pragma unroll
    for (int o = 1; o < 32; o <<= 1) {
        int t = __shfl_up_sync(0xffffffffu, pre, o);
        if (lane >= o) pre += t;
    }
    if (lane == 31) wsum[wid] = pre;
    __syncthreads();
    if (wid == 0) {
        int w = wsum[lane];
        int p = w;
#pragma unroll
        for (int o = 1; o < 32; o <<= 1) {
            int t = __shfl_up_sync(0xffffffffu, p, o);
            if (lane >= o) p += t;
        }
        wsum[lane] = p - w;
        if (lane == 31) g_bsum[blockIdx.x] = p;
    }
    __syncthreads();
    if (i < N_NODES) g_rowstart[i] = pre - v + wsum[wid];
}

__global__ void k_scan2() {
    int t = threadIdx.x;            // 128 threads
    int lane = t & 31, wid = t >> 5;
    __shared__ int ws[4];
    int v = (t < NB_SCAN) ? g_bsum[t] : 0;
    int pre = v;
#pragma unroll
    for (int o = 1; o < 32; o <<= 1) {
        int u = __shfl_up_sync(0xffffffffu, pre, o);
        if (lane >= o) pre += u;
    }
    if (lane == 31) ws[wid] = pre;
    __syncthreads();
    if (t == 0) {
        int r = 0;
#pragma unroll
        for (int k = 0; k < 4; k++) { int tmp = ws[k]; ws[k] = r; r += tmp; }
        g_rowstart[N_NODES] = N_EDGES;
    }
    __syncthreads();
    if (t < NB_SCAN) g_boff[t] = pre - v + ws[wid];
}

__global__ __launch_bounds__(1024) void k_scan3() {
    int i = blockIdx.x * 1024 + threadIdx.x;
    if (i < N_NODES) g_rowstart[i] += g_boff[blockIdx.x];
}

__global__ void k_fill(const void* __restrict__ ei) {
    for (int e = blockIdx.x * blockDim.x + threadIdx.x; e < N_EDGES;
         e += gridDim.x * blockDim.x) {
        int d = edge_at(ei, (long long)N_EDGES + e);
        int s = edge_at(ei, e);
        int pos = atomicAdd(&g_cursor[d], 1);
        g_csrc[g_rowstart[d] + pos] = s;
    }
}

// ============ helpers for wmma GEMMs ============

// convert 4 fp32 -> hi/lo packed bf16x2 pairs
__device__ __forceinline__ void split4(float4 v, uint2& hi, uint2& lo) {
    __nv_bfloat162 h01 = __floats2bfloat162_rn(v.x, v.y);
    __nv_bfloat162 h23 = __floats2bfloat162_rn(v.z, v.w);
    float r0 = v.x - __low2float(h01),  r1 = v.y - __high2float(h01);
    float r2 = v.z - __low2float(h23),  r3 = v.w - __high2float(h23);
    __nv_bfloat162 l01 = __floats2bfloat162_rn(r0, r1);
    __nv_bfloat162 l23 = __floats2bfloat162_rn(r2, r3);
    hi = make_uint2(*(uint32_t*)&h01, *(uint32_t*)&h23);
    lo = make_uint2(*(uint32_t*)&l01, *(uint32_t*)&l23);
}

// convert 128x128 fp32 (row stride 128, rows clamped) into hi/lo smem tiles
template <int NTHREADS>
__device__ __forceinline__ void conv_tile(const float* __restrict__ src, int row0,
                                          __nv_bfloat16* H, __nv_bfloat16* L, int tid) {
    for (int g = tid; g < 4096; g += NTHREADS) {
        int row = g >> 5, c4 = g & 31;
        int r = row0 + row;
        if (r >= N_NODES) r = N_NODES - 1;
        float4 v = ((const float4*)(src + (size_t)r * 128))[c4];
        uint2 hi, lo;
        split4(v, hi, lo);
        *(uint2*)(H + row * TS + c4 * 4) = hi;
        *(uint2*)(L + row * TS + c4 * 4) = lo;
    }
}

// ============ GEMM 1: y1 = x@Wl1 (fp16 out), yr = x@Wr1 (fp32 out) ============
// 512 threads. Warps 0-7 -> y1 (weights WL), warps 8-15 -> yr (weights WR).

__global__ __launch_bounds__(512) void k_gemm1(const float* __restrict__ x) {
    extern __shared__ __nv_bfloat16 sm[];
    __nv_bfloat16* AH  = sm;
    __nv_bfloat16* AL  = sm + TILE_ELEMS;
    __nv_bfloat16* WH0 = sm + 2 * TILE_ELEMS;  // WL hi
    __nv_bfloat16* WL0 = sm + 3 * TILE_ELEMS;  // WL lo
    __nv_bfloat16* WH1 = sm + 4 * TILE_ELEMS;  // WR hi
    __nv_bfloat16* WL1 = sm + 5 * TILE_ELEMS;  // WR lo

    int tid = threadIdx.x;
    int wid = tid >> 5, lane = tid & 31;
    int node0 = blockIdx.x * 128;

    // copy precomputed weight splits into padded smem (one uint4 = 8 bf16)
    {
        const __nv_bfloat16* srcs[4] = {g_wl1h, g_wl1l, g_wr1h, g_wr1l};
        __nv_bfloat16* dsts[4] = {WH0, WL0, WH1, WL1};
#pragma unroll
        for (int tgt = 0; tgt < 4; tgt++) {
            const uint4* s = (const uint4*)srcs[tgt];
            for (int g = tid; g < 2048; g += 512) {   // 128 rows x 16 uint4
                int row = g >> 4, c = g & 15;
                *(uint4*)(dsts[tgt] + row * TS + c * 8) = s[row * 16 + c];
            }
        }
    }
    conv_tile<512>(x, node0, AH, AL, tid);
    __syncthreads();

    int out_sel = wid >> 3;          // 0: y1, 1: yr
    int w = wid & 7;
    int wm = w & 3;                  // rows wm*32
    int wn = w >> 2;                 // cols wn*64
    const __nv_bfloat16* WH = out_sel ? WH1 : WH0;
    const __nv_bfloat16* WL = out_sel ? WL1 : WL0;

    wmma::fragment<wmma::accumulator, 16, 16, 16, float> C[2][4];
#pragma unroll
    for (int i = 0; i < 2; i++)
#pragma unroll
        for (int j = 0; j < 4; j++) wmma::fill_fragment(C[i][j], 0.0f);

#pragma unroll
    for (int k0 = 0; k0 < 8; k0++) {
        wmma::fragment<wmma::matrix_a, 16, 16, 16, __nv_bfloat16, wmma::row_major> ah[2], al[2];
#pragma unroll
        for (int i = 0; i < 2; i++) {
            wmma::load_matrix_sync(ah[i], AH + (wm * 32 + i * 16) * TS + k0 * 16, TS);
            wmma::load_matrix_sync(al[i], AL + (wm * 32 + i * 16) * TS + k0 * 16, TS);
        }
#pragma unroll
        for (int j = 0; j < 4; j++) {
            wmma::fragment<wmma::matrix_b, 16, 16, 16, __nv_bfloat16, wmma::row_major> bh, bl;
            wmma::load_matrix_sync(bh, WH + (k0 * 16) * TS + wn * 64 + j * 16, TS);
            wmma::load_matrix_sync(bl, WL + (k0 * 16) * TS + wn * 64 + j * 16, TS);
#pragma unroll
            for (int i = 0; i < 2; i++) {
                wmma::mma_sync(C[i][j], ah[i], bh, C[i][j]);
                wmma::mma_sync(C[i][j], al[i], bh, C[i][j]);
                wmma::mma_sync(C[i][j], ah[i], bl, C[i][j]);
            }
        }
    }

    if (out_sel == 1) {
        // yr stays fp32, direct fragment store
        float* dst = g_yr + (size_t)(node0 + wm * 32) * 128 + wn * 64;
#pragma unroll
        for (int i = 0; i < 2; i++)
#pragma unroll
            for (int j = 0; j < 4; j++)
                wmma::store_matrix_sync(dst + (size_t)i * 16 * 128 + j * 16, C[i][j],
                                        128, wmma::mem_row_major);
    }
    __syncthreads();   // all mma reads of weight smem done -> safe to reuse as staging
    if (out_sel == 0) {
        // stage fp32 frags in smem, convert to fp16, store coalesced
        float* eb = (float*)sm + (size_t)w * 2048;   // 32x64 fp32 per warp
#pragma unroll
        for (int i = 0; i < 2; i++)
#pragma unroll
            for (int j = 0; j < 4; j++)
                wmma::store_matrix_sync(eb + i * 16 * 64 + j * 16, C[i][j], 64,
                                        wmma::mem_row_major);
        __syncwarp();
        for (int e = lane; e < 1024; e += 32) {      // 1024 half2 units (32r x 32)
            int r = e >> 5, c2 = e & 31;
            float2 v = ((const float2*)eb)[e];
            __half2 hv = __floats2half2_rn(v.x, v.y);
            *(__half2*)(g_y1h + (size_t)(node0 + wm * 32 + r) * 128 + wn * 64 + c2 * 2) = hv;
        }
    }
}

// ====== FUSED: h = relu(mean-gather(y1) + yr + b1)  ->  pq = h @ [Wl2|Wr2] ======
// 512 threads per CTA, 128 nodes per CTA.
// Phase A: warp w gathers nodes w*8..w*8+7; writes h split hi/lo into smem tiles.
// Phase B: wmma gemm2 from smem; epilogue converts pq to fp16.

__global__ __launch_bounds__(512) void k_aggr_gemm2(const float* __restrict__ b1) {
    extern __shared__ __nv_bfloat16 sm[];
    __nv_bfloat16* AH  = sm;
    __nv_bfloat16* AL  = sm + TILE_ELEMS;
    __nv_bfloat16* W2H = sm + 2 * TILE_ELEMS;
    __nv_bfloat16* W2L = sm + 2 * TILE_ELEMS + 128 * T2S;

    int tid = threadIdx.x;
    int wid = tid >> 5, lane = tid & 31;
    int node0 = blockIdx.x * 128;

    // copy W2 splits (128x80) into padded smem
    {
        const uint4* sh = (const uint4*)g_w2h;
        const uint4* sl = (const uint4*)g_w2l;
        for (int g = tid; g < 1280; g += 512) {   // 128 rows x 10 uint4
            int row = g / 10, c = g % 10;
            *(uint4*)(W2H + row * T2S + c * 8) = sh[row * 10 + c];
            *(uint4*)(W2L + row * T2S + c * 8) = sl[row * 10 + c];
        }
    }

    // ---- Phase A: gather (y1 fp16) + relu, split into smem ----
    float4 bb = *(const float4*)(b1 + lane * 4);
#pragma unroll
    for (int i = 0; i < 8; i++) {
        int nl = wid * 8 + i;
        int node = node0 + nl;
        float4 h4 = make_float4(0.f, 0.f, 0.f, 0.f);
        if (node < N_NODES) {
            int rs = g_rowstart[node], re = g_rowstart[node + 1];
            float4 acc = make_float4(0.f, 0.f, 0.f, 0.f);
            for (int i0 = rs; i0 < re; i0 += 32) {
                int nv = min(32, re - i0);
                int s = (lane < nv) ? g_csrc[i0 + lane] : 0;
                int j = 0;
                for (; j + 8 <= nv; j += 8) {
                    uint2 u[8];
#pragma unroll
                    for (int t = 0; t < 8; t++) {
                        int sj = __shfl_sync(0xffffffffu, s, j + t);
                        u[t] = *(const uint2*)(g_y1h + (size_t)sj * 128 + lane * 4);
                    }
#pragma unroll
                    for (int t = 0; t < 8; t++) {
                        float2 a = __half22float2(*(const __half2*)&u[t].x);
                        float2 b = __half22float2(*(const __half2*)&u[t].y);
                        acc.x += a.x; acc.y += a.y; acc.z += b.x; acc.w += b.y;
                    }
                }
                for (; j < nv; j++) {
                    int sj = __shfl_sync(0xffffffffu, s, j);
                    uint2 u = *(const uint2*)(g_y1h + (size_t)sj * 128 + lane * 4);
                    float2 a = __half22float2(*(const __half2*)&u.x);
                    float2 b = __half22float2(*(const __half2*)&u.y);
                    acc.x += a.x; acc.y += a.y; acc.z += b.x; acc.w += b.y;
                }
            }
            float inv = 1.0f / fmaxf((float)(re - rs), 1.0f);
            float4 yr = *(const float4*)(g_yr + (size_t)node * 128 + lane * 4);
            h4.x = fmaxf(acc.x * inv + yr.x + bb.x, 0.f);
            h4.y = fmaxf(acc.y * inv + yr.y + bb.y, 0.f);
            h4.z = fmaxf(acc.z * inv + yr.z + bb.z, 0.f);
            h4.w = fmaxf(acc.w * inv + yr.w + bb.w, 0.f);
        }
        uint2 hi, lo;
        split4(h4, hi, lo);
        *(uint2*)(AH + nl * TS + lane * 4) = hi;
        *(uint2*)(AL + nl * TS + lane * 4) = lo;
    }
    __syncthreads();

    // ---- Phase B: wmma gemm2 ----
    int rblk = wid & 7;                 // rows rblk*16 .. +15
    int j0   = (wid < 8) ? 0 : 3;       // col frags {0,1,2} or {3,4}
    int nj   = (wid < 8) ? 3 : 2;

    wmma::fragment<wmma::accumulator, 16, 16, 16, float> C[3];
#pragma unroll
    for (int j = 0; j < 3; j++) wmma::fill_fragment(C[j], 0.0f);

#pragma unroll
    for (int k0 = 0; k0 < 8; k0++) {
        wmma::fragment<wmma::matrix_a, 16, 16, 16, __nv_bfloat16, wmma::row_major> ah, al;
        wmma::load_matrix_sync(ah, AH + (rblk * 16) * TS + k0 * 16, TS);
        wmma::load_matrix_sync(al, AL + (rblk * 16) * TS + k0 * 16, TS);
        for (int j = 0; j < nj; j++) {
            wmma::fragment<wmma::matrix_b, 16, 16, 16, __nv_bfloat16, wmma::row_major> bh, bl;
            wmma::load_matrix_sync(bh, W2H + (k0 * 16) * T2S + (j0 + j) * 16, T2S);
            wmma::load_matrix_sync(bl, W2L + (k0 * 16) * T2S + (j0 + j) * 16, T2S);
            wmma::mma_sync(C[j], ah, bh, C[j]);
            wmma::mma_sync(C[j], al, bh, C[j]);
            wmma::mma_sync(C[j], ah, bl, C[j]);
        }
    }
    __syncthreads();   // all mma reads of AH/AL done -> reuse as fp32 staging

    // ---- epilogue: stage fp32 pq (128x80) in smem, convert to fp16 ----
    float* stage = (float*)sm;          // 128*80*4 = 40960 B (fits in AH+AL region)
    for (int j = 0; j < nj; j++)
        wmma::store_matrix_sync(stage + (rblk * 16) * 80 + (j0 + j) * 16, C[j],
                                80, wmma::mem_row_major);
    __syncthreads();
    for (int g = tid; g < 5120; g += 512) {   // 128 rows x 40 half2
        int row = g / 40, c2 = g % 40;
        float2 v = ((const float2*)stage)[g];
        __half2 hv = __floats2half2_rn(v.x, v.y);
        *(__half2*)(g_pqh + (size_t)(node0 + row) * 80 + c2 * 2) = hv;
    }
}

// ---------- layer-2 aggregation + bias + log_softmax (warp per node, MLP x8) ----------

__global__ void k_final(const float* __restrict__ b2, float* __restrict__ out) {
    int warp = (blockIdx.x * blockDim.x + threadIdx.x) >> 5;
    if (warp >= N_NODES) return;
    int lane = threadIdx.x & 31;
    int rs = g_rowstart[warp], re = g_rowstart[warp + 1];
    float acc0 = 0.f, acc1 = 0.f;
    for (int i0 = rs; i0 < re; i0 += 32) {
        int nv = min(32, re - i0);
        int s = (lane < nv) ? g_csrc[i0 + lane] : 0;
        int j = 0;
        for (; j + 8 <= nv; j += 8) {
            __half a[8], c[8];
#pragma unroll
            for (int t = 0; t < 8; t++) {
                int sj = __shfl_sync(0xffffffffu, s, j + t);
                const __half* pr = g_pqh + (size_t)sj * 80;
                a[t] = pr[lane];
                c[t] = (lane < 8) ? pr[32 + lane] : __half(0.f);
            }
#pragma unroll
            for (int t = 0; t < 8; t++) {
                acc0 += __half2float(a[t]);
                acc1 += __half2float(c[t]);
            }
        }
        for (; j < nv; j++) {
            int sj = __shfl_sync(0xffffffffu, s, j);
            const __half* pr = g_pqh + (size_t)sj * 80;
            acc0 += __half2float(pr[lane]);
            if (lane < 8) acc1 += __half2float(pr[32 + lane]);
        }
    }
    float inv = 1.0f / fmaxf((float)(re - rs), 1.0f);
    const __half* qr = g_pqh + (size_t)warp * 80 + 40;
    float v0 = acc0 * inv + b2[lane] + __half2float(qr[lane]);
    float v1 = (lane < 8) ? (acc1 * inv + b2[32 + lane] + __half2float(qr[32 + lane]))
                          : -INFINITY;

    float mx = fmaxf(v0, v1);
#pragma unroll
    for (int o = 16; o; o >>= 1) mx = fmaxf(mx, __shfl_xor_sync(0xffffffffu, mx, o));
    float se = expf(v0 - mx) + ((lane < 8) ? expf(v1 - mx) : 0.f);
#pragma unroll
    for (int o = 16; o; o >>= 1) se += __shfl_xor_sync(0xffffffffu, se, o);
    float lse = logf(se);

    out[(size_t)warp * 40 + lane] = v0 - mx - lse;
    if (lane < 8) out[(size_t)warp * 40 + 32 + lane] = v1 - mx - lse;
}

// -------------------- launch --------------------

extern "C" void kernel_launch(void* const* d_in, const int* in_sizes, int n_in,
                              void* d_out, int out_size) {
    const float* x       = (const float*)d_in[0];
    const void*  ei      = d_in[1];
    const float* Wl1     = (const float*)d_in[2];
    const float* b1      = (const float*)d_in[3];
    const float* Wr1     = (const float*)d_in[4];
    const float* Wl2     = (const float*)d_in[5];
    const float* b2      = (const float*)d_in[6];
    const float* Wr2     = (const float*)d_in[7];
    float* out           = (float*)d_out;

    cudaFuncSetAttribute(k_gemm1, cudaFuncAttributeMaxDynamicSharedMemorySize, GEMM1_SMEM);
    cudaFuncSetAttribute(k_aggr_gemm2, cudaFuncAttributeMaxDynamicSharedMemorySize, FUSED_SMEM);

    // side stream + fork/join events (created once; deterministic work per call)
    static cudaStream_t s2 = nullptr;
    static cudaEvent_t ev_fork = nullptr, ev_join = nullptr;
    if (!s2) {
        cudaStreamCreateWithFlags(&s2, cudaStreamNonBlocking);
        cudaEventCreateWithFlags(&ev_fork, cudaEventDisableTiming);
        cudaEventCreateWithFlags(&ev_join, cudaEventDisableTiming);
    }

    k_detect<<<1, 256>>>((const int*)ei);
    k_prep_w<<<1, 1024>>>(Wl1, Wr1, Wl2, Wr2);

    // fork: gemm1 depends only on x + prep_w — run it alongside the CSR build
    cudaEventRecord(ev_fork, 0);
    cudaStreamWaitEvent(s2, ev_fork, 0);
    k_gemm1<<<N_PAD / 128, 512, GEMM1_SMEM, s2>>>(x);
    cudaEventRecord(ev_join, s2);

    // main stream: CSR build chain
    k_zero2<<<(N_NODES + 255) / 256, 256>>>();
    k_count<<<2048, 256>>>(ei);
    k_scan1<<<NB_SCAN, 1024>>>();
    k_scan2<<<1, 128>>>();
    k_scan3<<<NB_SCAN, 1024>>>();
    k_fill<<<2048, 256>>>(ei);

    // join: fused aggregation+gemm2 needs both CSR and y1/yr
    cudaStreamWaitEvent(0, ev_join, 0);
    k_aggr_gemm2<<<N_PAD / 128, 512, FUSED_SMEM>>>(b1);
    k_final<<<(N_NODES * 32 + 255) / 256, 256>>>(b2, out);
}

// round 11
// speedup vs baseline: 1.0092x; 1.0092x over previous
#include <cuda_runtime.h>
#include <cuda_bf16.h>
#include <cuda_fp16.h>
#include <mma.h>
#include <math.h>
#include <cstdint>

using namespace nvcuda;

#define N_NODES 100000
#define N_EDGES 1600000
#define N_PAD 100096                          // 782*128
#define NB_SCAN ((N_NODES + 1023) / 1024)     // 98

#define TS 136                                // smem A/W tile stride (bf16 elems)
#define T2S 80                                // smem W2 tile stride (160B rows)
#define TILE_ELEMS (128 * TS)

// gemm1 smem: AH, AL, WLH, WLL, WRH, WRL  (6 x 128 x 136 bf16)
#define GEMM1_SMEM (6 * TILE_ELEMS * 2)
// fused aggr+gemm2 smem: AH, AL (128x136 bf16) + W2H, W2L (128x80 bf16) = 108KB
#define FUSED_SMEM ((2 * 128 * TS + 2 * 128 * T2S) * 2)

// -------- scratch (static __device__ globals; no runtime alloc) ----------
__device__ int    g_is64;
__device__ int    g_degi[N_NODES];
__device__ int    g_cursor[N_NODES];
__device__ int    g_rowstart[N_NODES + 1];
__device__ int    g_bsum[NB_SCAN];
__device__ int    g_boff[NB_SCAN];
__device__ int    g_csrc[N_EDGES];
__device__ __half g_y1h[(size_t)N_PAD * 128]; // x @ Wl1  (fp16 — gathered 16x per node)
__device__ float  g_yr[(size_t)N_PAD * 128];  // x @ Wr1  (fp32 — read once per node)
__device__ float  g_pq[(size_t)N_PAD * 80];   // [p(40) | q(40)] per node (fp32)
// precomputed weight splits (bf16 hi/lo)
__device__ __nv_bfloat16 g_wl1h[16384], g_wl1l[16384];
__device__ __nv_bfloat16 g_wr1h[16384], g_wr1l[16384];
__device__ __nv_bfloat16 g_w2h[10240],  g_w2l[10240];   // [Wl2|Wr2] 128x80

// edge accessor: works for int32 or int64 edge_index
__device__ __forceinline__ int edge_at(const void* ei, long long idx) {
    if (g_is64) return (int)((const long long*)ei)[idx];
    return ((const int*)ei)[idx];
}

// -------------------- zero + dtype detect (merged) --------------------
__global__ void k_zero2(const int* __restrict__ ei32) {
    int i = blockIdx.x * blockDim.x + threadIdx.x;
    if (i < N_NODES) { g_degi[i] = 0; g_cursor[i] = 0; }
    if (blockIdx.x == 0) {
        __shared__ int nz;
        if (threadIdx.x == 0) nz = 0;
        __syncthreads();
        if (ei32[2 * threadIdx.x + 1] != 0) atomicAdd(&nz, 1);
        __syncthreads();
        if (threadIdx.x == 0) g_is64 = (nz == 0) ? 1 : 0;
    }
}

__device__ __forceinline__ void split1(float v, __nv_bfloat16& h, __nv_bfloat16& l) {
    h = __float2bfloat16_rn(v);
    l = __float2bfloat16_rn(v - __bfloat162float(h));
}

__global__ __launch_bounds__(1024) void k_prep_w(
    const float* __restrict__ Wl1, const float* __restrict__ Wr1,
    const float* __restrict__ Wl2, const float* __restrict__ Wr2) {
    for (int i = threadIdx.x; i < 16384; i += 1024) {
        split1(Wl1[i], g_wl1h[i], g_wl1l[i]);
        split1(Wr1[i], g_wr1h[i], g_wr1l[i]);
    }
    for (int i = threadIdx.x; i < 10240; i += 1024) {
        int k = i / 80, j = i % 80;
        float v = (j < 40) ? Wl2[k * 40 + j] : Wr2[k * 40 + (j - 40)];
        split1(v, g_w2h[i], g_w2l[i]);
    }
}

// -------------------- CSR build --------------------

__global__ void k_count(const void* __restrict__ ei) {
    for (int e = blockIdx.x * blockDim.x + threadIdx.x; e < N_EDGES;
         e += gridDim.x * blockDim.x) {
        int d = edge_at(ei, (long long)N_EDGES + e);
        atomicAdd(&g_degi[d], 1);
    }
}

__global__ __launch_bounds__(1024) void k_scan1() {
    __shared__ int wsum[32];
    int i = blockIdx.x * 1024 + threadIdx.x;
    int lane = threadIdx.x & 31, wid = threadIdx.x >> 5;
    int v = (i < N_NODES) ? g_degi[i] : 0;
    int pre = v;
#pragma unroll
    for (int o = 1; o < 32; o <<= 1) {
        int t = __shfl_up_sync(0xffffffffu, pre, o);
        if (lane >= o) pre += t;
    }
    if (lane == 31) wsum[wid] = pre;
    __syncthreads();
    if (wid == 0) {
        int w = wsum[lane];
        int p = w;
#pragma unroll
        for (int o = 1; o < 32; o <<= 1) {
            int t = __shfl_up_sync(0xffffffffu, p, o);
            if (lane >= o) p += t;
        }
        wsum[lane] = p - w;
        if (lane == 31) g_bsum[blockIdx.x] = p;
    }
    __syncthreads();
    if (i < N_NODES) g_rowstart[i] = pre - v + wsum[wid];
}

__global__ void k_scan2() {
    int t = threadIdx.x;            // 128 threads
    int lane = t & 31, wid = t >> 5;
    __shared__ int ws[4];
    int v = (t < NB_SCAN) ? g_bsum[t] : 0;
    int pre = v;
#pragma unroll
    for (int o = 1; o < 32; o <<= 1) {
        int u = __shfl_up_sync(0xffffffffu, pre, o);
        if (lane >= o) pre += u;
    }
    if (lane == 31) ws[wid] = pre;
    __syncthreads();
    if (t == 0) {
        int r = 0;
#pragma unroll
        for (int k = 0; k < 4; k++) { int tmp = ws[k]; ws[k] = r; r += tmp; }
        g_rowstart[N_NODES] = N_EDGES;
    }
    __syncthreads();
    if (t < NB_SCAN) g_boff[t] = pre - v + ws[wid];
}

__global__ __launch_bounds__(1024) void k_scan3() {
    int i = blockIdx.x * 1024 + threadIdx.x;
    if (i < N_NODES) g_rowstart[i] += g_boff[blockIdx.x];
}

__global__ void k_fill(const void* __restrict__ ei) {
    for (int e = blockIdx.x * blockDim.x + threadIdx.x; e < N_EDGES;
         e += gridDim.x * blockDim.x) {
        int d = edge_at(ei, (long long)N_EDGES + e);
        int s = edge_at(ei, e);
        int pos = atomicAdd(&g_cursor[d], 1);
        g_csrc[g_rowstart[d] + pos] = s;
    }
}

// ============ helpers for wmma GEMMs ============

// convert 4 fp32 -> hi/lo packed bf16x2 pairs
__device__ __forceinline__ void split4(float4 v, uint2& hi, uint2& lo) {
    __nv_bfloat162 h01 = __floats2bfloat162_rn(v.x, v.y);
    __nv_bfloat162 h23 = __floats2bfloat162_rn(v.z, v.w);
    float r0 = v.x - __low2float(h01),  r1 = v.y - __high2float(h01);
    float r2 = v.z - __low2float(h23),  r3 = v.w - __high2float(h23);
    __nv_bfloat162 l01 = __floats2bfloat162_rn(r0, r1);
    __nv_bfloat162 l23 = __floats2bfloat162_rn(r2, r3);
    hi = make_uint2(*(uint32_t*)&h01, *(uint32_t*)&h23);
    lo = make_uint2(*(uint32_t*)&l01, *(uint32_t*)&l23);
}

// convert 128x128 fp32 (row stride 128, rows clamped) into hi/lo smem tiles
template <int NTHREADS>
__device__ __forceinline__ void conv_tile(const float* __restrict__ src, int row0,
                                          __nv_bfloat16* H, __nv_bfloat16* L, int tid) {
    for (int g = tid; g < 4096; g += NTHREADS) {
        int row = g >> 5, c4 = g & 31;
        int r = row0 + row;
        if (r >= N_NODES) r = N_NODES - 1;
        float4 v = ((const float4*)(src + (size_t)r * 128))[c4];
        uint2 hi, lo;
        split4(v, hi, lo);
        *(uint2*)(H + row * TS + c4 * 4) = hi;
        *(uint2*)(L + row * TS + c4 * 4) = lo;
    }
}

// ============ GEMM 1: y1 = x@Wl1 (fp16 out), yr = x@Wr1 (fp32 out) ============
// 512 threads. Warps 0-7 -> y1 (weights WL), warps 8-15 -> yr (weights WR).

__global__ __launch_bounds__(512) void k_gemm1(const float* __restrict__ x) {
    extern __shared__ __nv_bfloat16 sm[];
    __nv_bfloat16* AH  = sm;
    __nv_bfloat16* AL  = sm + TILE_ELEMS;
    __nv_bfloat16* WH0 = sm + 2 * TILE_ELEMS;  // WL hi
    __nv_bfloat16* WL0 = sm + 3 * TILE_ELEMS;  // WL lo
    __nv_bfloat16* WH1 = sm + 4 * TILE_ELEMS;  // WR hi
    __nv_bfloat16* WL1 = sm + 5 * TILE_ELEMS;  // WR lo

    int tid = threadIdx.x;
    int wid = tid >> 5, lane = tid & 31;
    int node0 = blockIdx.x * 128;

    // copy precomputed weight splits into padded smem (one uint4 = 8 bf16)
    {
        const __nv_bfloat16* srcs[4] = {g_wl1h, g_wl1l, g_wr1h, g_wr1l};
        __nv_bfloat16* dsts[4] = {WH0, WL0, WH1, WL1};
#pragma unroll
        for (int tgt = 0; tgt < 4; tgt++) {
            const uint4* s = (const uint4*)srcs[tgt];
            for (int g = tid; g < 2048; g += 512) {   // 128 rows x 16 uint4
                int row = g >> 4, c = g & 15;
                *(uint4*)(dsts[tgt] + row * TS + c * 8) = s[row * 16 + c];
            }
        }
    }
    conv_tile<512>(x, node0, AH, AL, tid);
    __syncthreads();

    int out_sel = wid >> 3;          // 0: y1, 1: yr
    int w = wid & 7;
    int wm = w & 3;                  // rows wm*32
    int wn = w >> 2;                 // cols wn*64
    const __nv_bfloat16* WH = out_sel ? WH1 : WH0;
    const __nv_bfloat16* WL = out_sel ? WL1 : WL0;

    wmma::fragment<wmma::accumulator, 16, 16, 16, float> C[2][4];
#pragma unroll
    for (int i = 0; i < 2; i++)
#pragma unroll
        for (int j = 0; j < 4; j++) wmma::fill_fragment(C[i][j], 0.0f);

#pragma unroll
    for (int k0 = 0; k0 < 8; k0++) {
        wmma::fragment<wmma::matrix_a, 16, 16, 16, __nv_bfloat16, wmma::row_major> ah[2], al[2];
#pragma unroll
        for (int i = 0; i < 2; i++) {
            wmma::load_matrix_sync(ah[i], AH + (wm * 32 + i * 16) * TS + k0 * 16, TS);
            wmma::load_matrix_sync(al[i], AL + (wm * 32 + i * 16) * TS + k0 * 16, TS);
        }
#pragma unroll
        for (int j = 0; j < 4; j++) {
            wmma::fragment<wmma::matrix_b, 16, 16, 16, __nv_bfloat16, wmma::row_major> bh, bl;
            wmma::load_matrix_sync(bh, WH + (k0 * 16) * TS + wn * 64 + j * 16, TS);
            wmma::load_matrix_sync(bl, WL + (k0 * 16) * TS + wn * 64 + j * 16, TS);
#pragma unroll
            for (int i = 0; i < 2; i++) {
                wmma::mma_sync(C[i][j], ah[i], bh, C[i][j]);
                wmma::mma_sync(C[i][j], al[i], bh, C[i][j]);
                wmma::mma_sync(C[i][j], ah[i], bl, C[i][j]);
            }
        }
    }

    if (out_sel == 1) {
        // yr stays fp32, direct fragment store
        float* dst = g_yr + (size_t)(node0 + wm * 32) * 128 + wn * 64;
#pragma unroll
        for (int i = 0; i < 2; i++)
#pragma unroll
            for (int j = 0; j < 4; j++)
                wmma::store_matrix_sync(dst + (size_t)i * 16 * 128 + j * 16, C[i][j],
                                        128, wmma::mem_row_major);
    }
    __syncthreads();   // all mma reads of weight smem done -> safe to reuse as staging
    if (out_sel == 0) {
        // stage fp32 frags in smem, convert to fp16, store coalesced
        float* eb = (float*)sm + (size_t)w * 2048;   // 32x64 fp32 per warp
#pragma unroll
        for (int i = 0; i < 2; i++)
#pragma unroll
            for (int j = 0; j < 4; j++)
                wmma::store_matrix_sync(eb + i * 16 * 64 + j * 16, C[i][j], 64,
                                        wmma::mem_row_major);
        __syncwarp();
        for (int e = lane; e < 1024; e += 32) {      // 1024 half2 units (32r x 32)
            int r = e >> 5, c2 = e & 31;
            float2 v = ((const float2*)eb)[e];
            __half2 hv = __floats2half2_rn(v.x, v.y);
            *(__half2*)(g_y1h + (size_t)(node0 + wm * 32 + r) * 128 + wn * 64 + c2 * 2) = hv;
        }
    }
}

// ====== FUSED: h = relu(mean-gather(y1) + yr + b1)  ->  pq = h @ [Wl2|Wr2] ======
// 512 threads per CTA, 2 CTAs/SM (smem 108KB). 128 nodes per CTA.
// Phase A: warp w gathers nodes w*8..w*8+7; writes h split hi/lo into smem tiles.
// Phase B: wmma gemm2 from smem, fragments stored straight to fp32 g_pq.

__global__ __launch_bounds__(512, 2) void k_aggr_gemm2(const float* __restrict__ b1) {
    extern __shared__ __nv_bfloat16 sm[];
    __nv_bfloat16* AH  = sm;
    __nv_bfloat16* AL  = sm + TILE_ELEMS;
    __nv_bfloat16* W2H = sm + 2 * TILE_ELEMS;
    __nv_bfloat16* W2L = sm + 2 * TILE_ELEMS + 128 * T2S;

    int tid = threadIdx.x;
    int wid = tid >> 5, lane = tid & 31;
    int node0 = blockIdx.x * 128;

    // copy W2 splits (128x80) into smem (T2S=80 -> 160B rows, benign 2-way)
    {
        const uint4* sh = (const uint4*)g_w2h;
        const uint4* sl = (const uint4*)g_w2l;
        for (int g = tid; g < 1280; g += 512) {   // 128 rows x 10 uint4
            int row = g / 10, c = g % 10;
            *(uint4*)(W2H + row * T2S + c * 8) = sh[row * 10 + c];
            *(uint4*)(W2L + row * T2S + c * 8) = sl[row * 10 + c];
        }
    }

    // ---- Phase A: gather (y1 fp16) + relu, split into smem ----
    float4 bb = *(const float4*)(b1 + lane * 4);
#pragma unroll
    for (int i = 0; i < 8; i++) {
        int nl = wid * 8 + i;
        int node = node0 + nl;
        float4 h4 = make_float4(0.f, 0.f, 0.f, 0.f);
        if (node < N_NODES) {
            int rs = g_rowstart[node], re = g_rowstart[node + 1];
            float4 acc = make_float4(0.f, 0.f, 0.f, 0.f);
            for (int i0 = rs; i0 < re; i0 += 32) {
                int nv = min(32, re - i0);
                int s = (lane < nv) ? g_csrc[i0 + lane] : 0;
                int j = 0;
                for (; j + 8 <= nv; j += 8) {
                    uint2 u[8];
#pragma unroll
                    for (int t = 0; t < 8; t++) {
                        int sj = __shfl_sync(0xffffffffu, s, j + t);
                        u[t] = *(const uint2*)(g_y1h + (size_t)sj * 128 + lane * 4);
                    }
#pragma unroll
                    for (int t = 0; t < 8; t++) {
                        float2 a = __half22float2(*(const __half2*)&u[t].x);
                        float2 b = __half22float2(*(const __half2*)&u[t].y);
                        acc.x += a.x; acc.y += a.y; acc.z += b.x; acc.w += b.y;
                    }
                }
                for (; j < nv; j++) {
                    int sj = __shfl_sync(0xffffffffu, s, j);
                    uint2 u = *(const uint2*)(g_y1h + (size_t)sj * 128 + lane * 4);
                    float2 a = __half22float2(*(const __half2*)&u.x);
                    float2 b = __half22float2(*(const __half2*)&u.y);
                    acc.x += a.x; acc.y += a.y; acc.z += b.x; acc.w += b.y;
                }
            }
            float inv = 1.0f / fmaxf((float)(re - rs), 1.0f);
            float4 yr = *(const float4*)(g_yr + (size_t)node * 128 + lane * 4);
            h4.x = fmaxf(acc.x * inv + yr.x + bb.x, 0.f);
            h4.y = fmaxf(acc.y * inv + yr.y + bb.y, 0.f);
            h4.z = fmaxf(acc.z * inv + yr.z + bb.z, 0.f);
            h4.w = fmaxf(acc.w * inv + yr.w + bb.w, 0.f);
        }
        uint2 hi, lo;
        split4(h4, hi, lo);
        *(uint2*)(AH + nl * TS + lane * 4) = hi;
        *(uint2*)(AL + nl * TS + lane * 4) = lo;
    }
    __syncthreads();

    // ---- Phase B: wmma gemm2 ----
    int rblk = wid & 7;                 // rows rblk*16 .. +15
    int j0   = (wid < 8) ? 0 : 3;       // col frags {0,1,2} or {3,4}
    int nj   = (wid < 8) ? 3 : 2;

    wmma::fragment<wmma::accumulator, 16, 16, 16, float> C[3];
#pragma unroll
    for (int j = 0; j < 3; j++) wmma::fill_fragment(C[j], 0.0f);

#pragma unroll
    for (int k0 = 0; k0 < 8; k0++) {
        wmma::fragment<wmma::matrix_a, 16, 16, 16, __nv_bfloat16, wmma::row_major> ah, al;
        wmma::load_matrix_sync(ah, AH + (rblk * 16) * TS + k0 * 16, TS);
        wmma::load_matrix_sync(al, AL + (rblk * 16) * TS + k0 * 16, TS);
        for (int j = 0; j < nj; j++) {
            wmma::fragment<wmma::matrix_b, 16, 16, 16, __nv_bfloat16, wmma::row_major> bh, bl;
            wmma::load_matrix_sync(bh, W2H + (k0 * 16) * T2S + (j0 + j) * 16, T2S);
            wmma::load_matrix_sync(bl, W2L + (k0 * 16) * T2S + (j0 + j) * 16, T2S);
            wmma::mma_sync(C[j], ah, bh, C[j]);
            wmma::mma_sync(C[j], al, bh, C[j]);
            wmma::mma_sync(C[j], ah, bl, C[j]);
        }
    }

    float* dst = g_pq + (size_t)(node0 + rblk * 16) * 80;
    for (int j = 0; j < nj; j++)
        wmma::store_matrix_sync(dst + (j0 + j) * 16, C[j], 80, wmma::mem_row_major);
}

// ---------- layer-2 aggregation + bias + log_softmax (warp per node, MLP x4) ----------

__global__ void k_final(const float* __restrict__ b2, float* __restrict__ out) {
    int warp = (blockIdx.x * blockDim.x + threadIdx.x) >> 5;
    if (warp >= N_NODES) return;
    int lane = threadIdx.x & 31;
    int rs = g_rowstart[warp], re = g_rowstart[warp + 1];
    float acc0 = 0.f, acc1 = 0.f;
    for (int i0 = rs; i0 < re; i0 += 32) {
        int nv = min(32, re - i0);
        int s = (lane < nv) ? g_csrc[i0 + lane] : 0;
        int j = 0;
        for (; j + 4 <= nv; j += 4) {
            int s0 = __shfl_sync(0xffffffffu, s, j);
            int s1 = __shfl_sync(0xffffffffu, s, j + 1);
            int s2 = __shfl_sync(0xffffffffu, s, j + 2);
            int s3 = __shfl_sync(0xffffffffu, s, j + 3);
            const float* p0 = g_pq + (size_t)s0 * 80;
            const float* p1 = g_pq + (size_t)s1 * 80;
            const float* p2 = g_pq + (size_t)s2 * 80;
            const float* p3 = g_pq + (size_t)s3 * 80;
            float a0 = p0[lane], a1 = p1[lane], a2 = p2[lane], a3 = p3[lane];
            acc0 += (a0 + a1) + (a2 + a3);
            if (lane < 8) {
                float c0 = p0[32 + lane], c1 = p1[32 + lane];
                float c2 = p2[32 + lane], c3 = p3[32 + lane];
                acc1 += (c0 + c1) + (c2 + c3);
            }
        }
        for (; j < nv; j++) {
            int sj = __shfl_sync(0xffffffffu, s, j);
            const float* pr = g_pq + (size_t)sj * 80;
            acc0 += pr[lane];
            if (lane < 8) acc1 += pr[32 + lane];
        }
    }
    float inv = 1.0f / fmaxf((float)(re - rs), 1.0f);
    const float* qr = g_pq + (size_t)warp * 80 + 40;
    float v0 = acc0 * inv + b2[lane] + qr[lane];
    float v1 = (lane < 8) ? (acc1 * inv + b2[32 + lane] + qr[32 + lane]) : -INFINITY;

    float mx = fmaxf(v0, v1);
#pragma unroll
    for (int o = 16; o; o >>= 1) mx = fmaxf(mx, __shfl_xor_sync(0xffffffffu, mx, o));
    float se = expf(v0 - mx) + ((lane < 8) ? expf(v1 - mx) : 0.f);
#pragma unroll
    for (int o = 16; o; o >>= 1) se += __shfl_xor_sync(0xffffffffu, se, o);
    float lse = logf(se);

    out[(size_t)warp * 40 + lane] = v0 - mx - lse;
    if (lane < 8) out[(size_t)warp * 40 + 32 + lane] = v1 - mx - lse;
}

// -------------------- launch --------------------

extern "C" void kernel_launch(void* const* d_in, const int* in_sizes, int n_in,
                              void* d_out, int out_size) {
    const float* x       = (const float*)d_in[0];
    const void*  ei      = d_in[1];
    const float* Wl1     = (const float*)d_in[2];
    const float* b1      = (const float*)d_in[3];
    const float* Wr1     = (const float*)d_in[4];
    const float* Wl2     = (const float*)d_in[5];
    const float* b2      = (const float*)d_in[6];
    const float* Wr2     = (const float*)d_in[7];
    float* out           = (float*)d_out;

    cudaFuncSetAttribute(k_gemm1, cudaFuncAttributeMaxDynamicSharedMemorySize, GEMM1_SMEM);
    cudaFuncSetAttribute(k_aggr_gemm2, cudaFuncAttributeMaxDynamicSharedMemorySize, FUSED_SMEM);

    // side stream + fork/join events (created once; deterministic work per call)
    static cudaStream_t s2 = nullptr;
    static cudaEvent_t ev_fork = nullptr, ev_join = nullptr;
    if (!s2) {
        cudaStreamCreateWithFlags(&s2, cudaStreamNonBlocking);
        cudaEventCreateWithFlags(&ev_fork, cudaEventDisableTiming);
        cudaEventCreateWithFlags(&ev_join, cudaEventDisableTiming);
    }

    k_prep_w<<<1, 1024>>>(Wl1, Wr1, Wl2, Wr2);

    // fork: gemm1 depends only on x + prep_w — run it alongside the CSR build
    cudaEventRecord(ev_fork, 0);
    cudaStreamWaitEvent(s2, ev_fork, 0);
    k_gemm1<<<N_PAD / 128, 512, GEMM1_SMEM, s2>>>(x);
    cudaEventRecord(ev_join, s2);

    // main stream: CSR build chain (zero2 also does the dtype detect)
    k_zero2<<<(N_NODES + 255) / 256, 256>>>((const int*)ei);
    k_count<<<2048, 256>>>(ei);
    k_scan1<<<NB_SCAN, 1024>>>();
    k_scan2<<<1, 128>>>();
    k_scan3<<<NB_SCAN, 1024>>>();
    k_fill<<<2048, 256>>>(ei);

    // join: fused aggregation+gemm2 needs both CSR and y1/yr
    cudaStreamWaitEvent(0, ev_join, 0);
    k_aggr_gemm2<<<N_PAD / 128, 512, FUSED_SMEM>>>(b1);
    k_final<<<(N_NODES * 32 + 255) / 256, 256>>>(b2, out);
}

// round 12
// speedup vs baseline: 1.0289x; 1.0195x over previous
#include <cuda_runtime.h>
#include <cuda_bf16.h>
#include <cuda_fp16.h>
#include <mma.h>
#include <math.h>
#include <cstdint>

using namespace nvcuda;

#define N_NODES 100000
#define N_EDGES 1600000
#define N_PAD 100096                          // 782*128
#define NB_SCAN ((N_NODES + 1023) / 1024)     // 98

#define TS 136                                // smem A/W tile stride (bf16 elems)
#define T2S 80                                // smem W2 tile stride (160B rows)
#define TILE_ELEMS (128 * TS)

// gemm1 smem: AH, AL, WLH, WLL, WRH, WRL  (6 x 128 x 136 bf16)
#define GEMM1_SMEM (6 * TILE_ELEMS * 2)
// fused aggr+gemm2 smem: AH, AL (128x136 bf16) + W2H, W2L (128x80 bf16) = 108KB
#define FUSED_SMEM ((2 * 128 * TS + 2 * 128 * T2S) * 2)

// -------- scratch (static __device__ globals; no runtime alloc) ----------
__device__ int    g_is64;
__device__ int    g_degi[N_NODES];
__device__ int    g_cursor[N_NODES];
__device__ int    g_rowstart[N_NODES + 1];
__device__ int    g_bsum[NB_SCAN];
__device__ int    g_boff[NB_SCAN];
__device__ int    g_csrc[N_EDGES];
__device__ __half g_y1h[(size_t)N_PAD * 128]; // x @ Wl1  (fp16 — gathered 16x per node)
__device__ float  g_yr[(size_t)N_PAD * 128];  // x @ Wr1  (fp32 — read once per node)
__device__ __half g_pqh[(size_t)N_PAD * 80];  // [p(40) | q(40)] per node (fp16)
// precomputed weight splits (bf16 hi/lo)
__device__ __nv_bfloat16 g_wl1h[16384], g_wl1l[16384];
__device__ __nv_bfloat16 g_wr1h[16384], g_wr1l[16384];
__device__ __nv_bfloat16 g_w2h[10240],  g_w2l[10240];   // [Wl2|Wr2] 128x80

// edge accessor: works for int32 or int64 edge_index
__device__ __forceinline__ int edge_at(const void* ei, long long idx) {
    if (g_is64) return (int)((const long long*)ei)[idx];
    return ((const int*)ei)[idx];
}

// -------------------- zero + dtype detect (merged) --------------------
__global__ void k_zero2(const int* __restrict__ ei32) {
    int i = blockIdx.x * blockDim.x + threadIdx.x;
    if (i < N_NODES) { g_degi[i] = 0; g_cursor[i] = 0; }
    if (blockIdx.x == 0) {
        __shared__ int nz;
        if (threadIdx.x == 0) nz = 0;
        __syncthreads();
        if (ei32[2 * threadIdx.x + 1] != 0) atomicAdd(&nz, 1);
        __syncthreads();
        if (threadIdx.x == 0) g_is64 = (nz == 0) ? 1 : 0;
    }
}

__device__ __forceinline__ void split1(float v, __nv_bfloat16& h, __nv_bfloat16& l) {
    h = __float2bfloat16_rn(v);
    l = __float2bfloat16_rn(v - __bfloat162float(h));
}

__global__ __launch_bounds__(1024) void k_prep_w(
    const float* __restrict__ Wl1, const float* __restrict__ Wr1,
    const float* __restrict__ Wl2, const float* __restrict__ Wr2) {
    for (int i = threadIdx.x; i < 16384; i += 1024) {
        split1(Wl1[i], g_wl1h[i], g_wl1l[i]);
        split1(Wr1[i], g_wr1h[i], g_wr1l[i]);
    }
    for (int i = threadIdx.x; i < 10240; i += 1024) {
        int k = i / 80, j = i % 80;
        float v = (j < 40) ? Wl2[k * 40 + j] : Wr2[k * 40 + (j - 40)];
        split1(v, g_w2h[i], g_w2l[i]);
    }
}

// -------------------- CSR build --------------------

__global__ void k_count(const void* __restrict__ ei) {
    for (int e = blockIdx.x * blockDim.x + threadIdx.x; e < N_EDGES;
         e += gridDim.x * blockDim.x) {
        int d = edge_at(ei, (long long)N_EDGES + e);
        atomicAdd(&g_degi[d], 1);
    }
}

__global__ __launch_bounds__(1024) void k_scan1() {
    __shared__ int wsum[32];
    int i = blockIdx.x * 1024 + threadIdx.x;
    int lane = threadIdx.x & 31, wid = threadIdx.x >> 5;
    int v = (i < N_NODES) ? g_degi[i] : 0;
    int pre = v;
#pragma unroll
    for (int o = 1; o < 32; o <<= 1) {
        int t = __shfl_up_sync(0xffffffffu, pre, o);
        if (lane >= o) pre += t;
    }
    if (lane == 31) wsum[wid] = pre;
    __syncthreads();
    if (wid == 0) {
        int w = wsum[lane];
        int p = w;
#pragma unroll
        for (int o = 1; o < 32; o <<= 1) {
            int t = __shfl_up_sync(0xffffffffu, p, o);
            if (lane >= o) p += t;
        }
        wsum[lane] = p - w;
        if (lane == 31) g_bsum[blockIdx.x] = p;
    }
    __syncthreads();
    if (i < N_NODES) g_rowstart[i] = pre - v + wsum[wid];
}

__global__ void k_scan2() {
    int t = threadIdx.x;            // 128 threads
    int lane = t & 31, wid = t >> 5;
    __shared__ int ws[4];
    int v = (t < NB_SCAN) ? g_bsum[t] : 0;
    int pre = v;
#pragma unroll
    for (int o = 1; o < 32; o <<= 1) {
        int u = __shfl_up_sync(0xffffffffu, pre, o);
        if (lane >= o) pre += u;
    }
    if (lane == 31) ws[wid] = pre;
    __syncthreads();
    if (t == 0) {
        int r = 0;
#pragma unroll
        for (int k = 0; k < 4; k++) { int tmp = ws[k]; ws[k] = r; r += tmp; }
        g_rowstart[N_NODES] = N_EDGES;
    }
    __syncthreads();
    if (t < NB_SCAN) g_boff[t] = pre - v + ws[wid];
}

__global__ __launch_bounds__(1024) void k_scan3() {
    int i = blockIdx.x * 1024 + threadIdx.x;
    if (i < N_NODES) g_rowstart[i] += g_boff[blockIdx.x];
}

__global__ void k_fill(const void* __restrict__ ei) {
    for (int e = blockIdx.x * blockDim.x + threadIdx.x; e < N_EDGES;
         e += gridDim.x * blockDim.x) {
        int d = edge_at(ei, (long long)N_EDGES + e);
        int s = edge_at(ei, e);
        int pos = atomicAdd(&g_cursor[d], 1);
        g_csrc[g_rowstart[d] + pos] = s;
    }
}

// ============ helpers for wmma GEMMs ============

// convert 4 fp32 -> hi/lo packed bf16x2 pairs
__device__ __forceinline__ void split4(float4 v, uint2& hi, uint2& lo) {
    __nv_bfloat162 h01 = __floats2bfloat162_rn(v.x, v.y);
    __nv_bfloat162 h23 = __floats2bfloat162_rn(v.z, v.w);
    float r0 = v.x - __low2float(h01),  r1 = v.y - __high2float(h01);
    float r2 = v.z - __low2float(h23),  r3 = v.w - __high2float(h23);
    __nv_bfloat162 l01 = __floats2bfloat162_rn(r0, r1);
    __nv_bfloat162 l23 = __floats2bfloat162_rn(r2, r3);
    hi = make_uint2(*(uint32_t*)&h01, *(uint32_t*)&h23);
    lo = make_uint2(*(uint32_t*)&l01, *(uint32_t*)&l23);
}

// convert 128x128 fp32 (row stride 128, rows clamped) into hi/lo smem tiles
template <int NTHREADS>
__device__ __forceinline__ void conv_tile(const float* __restrict__ src, int row0,
                                          __nv_bfloat16* H, __nv_bfloat16* L, int tid) {
    for (int g = tid; g < 4096; g += NTHREADS) {
        int row = g >> 5, c4 = g & 31;
        int r = row0 + row;
        if (r >= N_NODES) r = N_NODES - 1;
        float4 v = ((const float4*)(src + (size_t)r * 128))[c4];
        uint2 hi, lo;
        split4(v, hi, lo);
        *(uint2*)(H + row * TS + c4 * 4) = hi;
        *(uint2*)(L + row * TS + c4 * 4) = lo;
    }
}

// ============ GEMM 1: y1 = x@Wl1 (fp16 out), yr = x@Wr1 (fp32 out) ============
// 512 threads. Warps 0-7 -> y1 (weights WL), warps 8-15 -> yr (weights WR).

__global__ __launch_bounds__(512) void k_gemm1(const float* __restrict__ x) {
    extern __shared__ __nv_bfloat16 sm[];
    __nv_bfloat16* AH  = sm;
    __nv_bfloat16* AL  = sm + TILE_ELEMS;
    __nv_bfloat16* WH0 = sm + 2 * TILE_ELEMS;  // WL hi
    __nv_bfloat16* WL0 = sm + 3 * TILE_ELEMS;  // WL lo
    __nv_bfloat16* WH1 = sm + 4 * TILE_ELEMS;  // WR hi
    __nv_bfloat16* WL1 = sm + 5 * TILE_ELEMS;  // WR lo

    int tid = threadIdx.x;
    int wid = tid >> 5, lane = tid & 31;
    int node0 = blockIdx.x * 128;

    // copy precomputed weight splits into padded smem (one uint4 = 8 bf16)
    {
        const __nv_bfloat16* srcs[4] = {g_wl1h, g_wl1l, g_wr1h, g_wr1l};
        __nv_bfloat16* dsts[4] = {WH0, WL0, WH1, WL1};
#pragma unroll
        for (int tgt = 0; tgt < 4; tgt++) {
            const uint4* s = (const uint4*)srcs[tgt];
            for (int g = tid; g < 2048; g += 512) {   // 128 rows x 16 uint4
                int row = g >> 4, c = g & 15;
                *(uint4*)(dsts[tgt] + row * TS + c * 8) = s[row * 16 + c];
            }
        }
    }
    conv_tile<512>(x, node0, AH, AL, tid);
    __syncthreads();

    int out_sel = wid >> 3;          // 0: y1, 1: yr
    int w = wid & 7;
    int wm = w & 3;                  // rows wm*32
    int wn = w >> 2;                 // cols wn*64
    const __nv_bfloat16* WH = out_sel ? WH1 : WH0;
    const __nv_bfloat16* WL = out_sel ? WL1 : WL0;

    wmma::fragment<wmma::accumulator, 16, 16, 16, float> C[2][4];
#pragma unroll
    for (int i = 0; i < 2; i++)
#pragma unroll
        for (int j = 0; j < 4; j++) wmma::fill_fragment(C[i][j], 0.0f);

#pragma unroll
    for (int k0 = 0; k0 < 8; k0++) {
        wmma::fragment<wmma::matrix_a, 16, 16, 16, __nv_bfloat16, wmma::row_major> ah[2], al[2];
#pragma unroll
        for (int i = 0; i < 2; i++) {
            wmma::load_matrix_sync(ah[i], AH + (wm * 32 + i * 16) * TS + k0 * 16, TS);
            wmma::load_matrix_sync(al[i], AL + (wm * 32 + i * 16) * TS + k0 * 16, TS);
        }
#pragma unroll
        for (int j = 0; j < 4; j++) {
            wmma::fragment<wmma::matrix_b, 16, 16, 16, __nv_bfloat16, wmma::row_major> bh, bl;
            wmma::load_matrix_sync(bh, WH + (k0 * 16) * TS + wn * 64 + j * 16, TS);
            wmma::load_matrix_sync(bl, WL + (k0 * 16) * TS + wn * 64 + j * 16, TS);
#pragma unroll
            for (int i = 0; i < 2; i++) {
                wmma::mma_sync(C[i][j], ah[i], bh, C[i][j]);
                wmma::mma_sync(C[i][j], al[i], bh, C[i][j]);
                wmma::mma_sync(C[i][j], ah[i], bl, C[i][j]);
            }
        }
    }

    if (out_sel == 1) {
        // yr stays fp32, direct fragment store
        float* dst = g_yr + (size_t)(node0 + wm * 32) * 128 + wn * 64;
#pragma unroll
        for (int i = 0; i < 2; i++)
#pragma unroll
            for (int j = 0; j < 4; j++)
                wmma::store_matrix_sync(dst + (size_t)i * 16 * 128 + j * 16, C[i][j],
                                        128, wmma::mem_row_major);
    }
    __syncthreads();   // all mma reads of weight smem done -> safe to reuse as staging
    if (out_sel == 0) {
        // stage fp32 frags in smem, convert to fp16, store coalesced
        float* eb = (float*)sm + (size_t)w * 2048;   // 32x64 fp32 per warp
#pragma unroll
        for (int i = 0; i < 2; i++)
#pragma unroll
            for (int j = 0; j < 4; j++)
                wmma::store_matrix_sync(eb + i * 16 * 64 + j * 16, C[i][j], 64,
                                        wmma::mem_row_major);
        __syncwarp();
        for (int e = lane; e < 1024; e += 32) {      // 1024 half2 units (32r x 32)
            int r = e >> 5, c2 = e & 31;
            float2 v = ((const float2*)eb)[e];
            __half2 hv = __floats2half2_rn(v.x, v.y);
            *(__half2*)(g_y1h + (size_t)(node0 + wm * 32 + r) * 128 + wn * 64 + c2 * 2) = hv;
        }
    }
}

// ====== FUSED: h = relu(mean-gather(y1) + yr + b1)  ->  pq = h @ [Wl2|Wr2] ======
// 512 threads per CTA, 2 CTAs/SM (smem 108KB). 128 nodes per CTA.
// Phase A: warp w gathers nodes w*8..w*8+7; writes h split hi/lo into smem tiles.
// Phase B: wmma gemm2 from smem; epilogue converts pq to fp16 (g_pqh).

__global__ __launch_bounds__(512, 2) void k_aggr_gemm2(const float* __restrict__ b1) {
    extern __shared__ __nv_bfloat16 sm[];
    __nv_bfloat16* AH  = sm;
    __nv_bfloat16* AL  = sm + TILE_ELEMS;
    __nv_bfloat16* W2H = sm + 2 * TILE_ELEMS;
    __nv_bfloat16* W2L = sm + 2 * TILE_ELEMS + 128 * T2S;

    int tid = threadIdx.x;
    int wid = tid >> 5, lane = tid & 31;
    int node0 = blockIdx.x * 128;

    // copy W2 splits (128x80) into smem (T2S=80 -> 160B rows, benign 2-way)
    {
        const uint4* sh = (const uint4*)g_w2h;
        const uint4* sl = (const uint4*)g_w2l;
        for (int g = tid; g < 1280; g += 512) {   // 128 rows x 10 uint4
            int row = g / 10, c = g % 10;
            *(uint4*)(W2H + row * T2S + c * 8) = sh[row * 10 + c];
            *(uint4*)(W2L + row * T2S + c * 8) = sl[row * 10 + c];
        }
    }

    // ---- Phase A: gather (y1 fp16) + relu, split into smem ----
    float4 bb = *(const float4*)(b1 + lane * 4);
#pragma unroll
    for (int i = 0; i < 8; i++) {
        int nl = wid * 8 + i;
        int node = node0 + nl;
        float4 h4 = make_float4(0.f, 0.f, 0.f, 0.f);
        if (node < N_NODES) {
            int rs = g_rowstart[node], re = g_rowstart[node + 1];
            float4 acc = make_float4(0.f, 0.f, 0.f, 0.f);
            for (int i0 = rs; i0 < re; i0 += 32) {
                int nv = min(32, re - i0);
                int s = (lane < nv) ? g_csrc[i0 + lane] : 0;
                int j = 0;
                for (; j + 8 <= nv; j += 8) {
                    uint2 u[8];
#pragma unroll
                    for (int t = 0; t < 8; t++) {
                        int sj = __shfl_sync(0xffffffffu, s, j + t);
                        u[t] = *(const uint2*)(g_y1h + (size_t)sj * 128 + lane * 4);
                    }
#pragma unroll
                    for (int t = 0; t < 8; t++) {
                        float2 a = __half22float2(*(const __half2*)&u[t].x);
                        float2 b = __half22float2(*(const __half2*)&u[t].y);
                        acc.x += a.x; acc.y += a.y; acc.z += b.x; acc.w += b.y;
                    }
                }
                for (; j < nv; j++) {
                    int sj = __shfl_sync(0xffffffffu, s, j);
                    uint2 u = *(const uint2*)(g_y1h + (size_t)sj * 128 + lane * 4);
                    float2 a = __half22float2(*(const __half2*)&u.x);
                    float2 b = __half22float2(*(const __half2*)&u.y);
                    acc.x += a.x; acc.y += a.y; acc.z += b.x; acc.w += b.y;
                }
            }
            float inv = 1.0f / fmaxf((float)(re - rs), 1.0f);
            float4 yr = *(const float4*)(g_yr + (size_t)node * 128 + lane * 4);
            h4.x = fmaxf(acc.x * inv + yr.x + bb.x, 0.f);
            h4.y = fmaxf(acc.y * inv + yr.y + bb.y, 0.f);
            h4.z = fmaxf(acc.z * inv + yr.z + bb.z, 0.f);
            h4.w = fmaxf(acc.w * inv + yr.w + bb.w, 0.f);
        }
        uint2 hi, lo;
        split4(h4, hi, lo);
        *(uint2*)(AH + nl * TS + lane * 4) = hi;
        *(uint2*)(AL + nl * TS + lane * 4) = lo;
    }
    __syncthreads();

    // ---- Phase B: wmma gemm2 ----
    int rblk = wid & 7;                 // rows rblk*16 .. +15
    int j0   = (wid < 8) ? 0 : 3;       // col frags {0,1,2} or {3,4}
    int nj   = (wid < 8) ? 3 : 2;

    wmma::fragment<wmma::accumulator, 16, 16, 16, float> C[3];
#pragma unroll
    for (int j = 0; j < 3; j++) wmma::fill_fragment(C[j], 0.0f);

#pragma unroll
    for (int k0 = 0; k0 < 8; k0++) {
        wmma::fragment<wmma::matrix_a, 16, 16, 16, __nv_bfloat16, wmma::row_major> ah, al;
        wmma::load_matrix_sync(ah, AH + (rblk * 16) * TS + k0 * 16, TS);
        wmma::load_matrix_sync(al, AL + (rblk * 16) * TS + k0 * 16, TS);
        for (int j = 0; j < nj; j++) {
            wmma::fragment<wmma::matrix_b, 16, 16, 16, __nv_bfloat16, wmma::row_major> bh, bl;
            wmma::load_matrix_sync(bh, W2H + (k0 * 16) * T2S + (j0 + j) * 16, T2S);
            wmma::load_matrix_sync(bl, W2L + (k0 * 16) * T2S + (j0 + j) * 16, T2S);
            wmma::mma_sync(C[j], ah, bh, C[j]);
            wmma::mma_sync(C[j], al, bh, C[j]);
            wmma::mma_sync(C[j], ah, bl, C[j]);
        }
    }
    __syncthreads();   // all mma reads of AH/AL done -> reuse as fp32 staging

    // ---- epilogue: stage fp32 pq (128x80) in smem, convert to fp16 ----
    float* stage = (float*)sm;          // 128*80*4 = 40960 B (fits in AH+AL region)
    for (int j = 0; j < nj; j++)
        wmma::store_matrix_sync(stage + (rblk * 16) * 80 + (j0 + j) * 16, C[j],
                                80, wmma::mem_row_major);
    __syncthreads();
    for (int g = tid; g < 5120; g += 512) {   // 128 rows x 40 half2
        int row = g / 40, c2 = g % 40;
        float2 v = ((const float2*)stage)[g];
        __half2 hv = __floats2half2_rn(v.x, v.y);
        *(__half2*)(g_pqh + (size_t)(node0 + row) * 80 + c2 * 2) = hv;
    }
}

// ---------- layer-2 aggregation + bias + log_softmax ----------
// warp per node; 3 lane-groups of 10 gather 3 edges per load instruction.
// p-row = 40 fp16 = 80B = uint2 x 10 lanes; 2 triples unrolled for MLP.

__global__ void k_final(const float* __restrict__ b2, float* __restrict__ out) {
    int warp = (blockIdx.x * blockDim.x + threadIdx.x) >> 5;
    if (warp >= N_NODES) return;
    int lane = threadIdx.x & 31;
    int g  = lane / 10;          // 0,1,2 (lanes 30,31 idle)
    int gl = lane % 10;
    bool active = lane < 30;
    int rs = g_rowstart[warp], re = g_rowstart[warp + 1];
    float acc[4] = {0.f, 0.f, 0.f, 0.f};

    for (int i0 = rs; i0 < re; i0 += 32) {
        int nv = min(32, re - i0);
        int s = (lane < nv) ? g_csrc[i0 + lane] : 0;
        for (int j = 0; j < nv; j += 6) {
            int e0 = j + g, e1 = j + 3 + g;
            int src0 = __shfl_sync(0xffffffffu, s, (e0 < nv) ? e0 : 0);
            int src1 = __shfl_sync(0xffffffffu, s, (e1 < nv) ? e1 : 0);
            bool v0 = active && (e0 < nv);
            bool v1 = active && (e1 < nv);
            uint2 u0 = v0 ? *(const uint2*)(g_pqh + (size_t)src0 * 80 + gl * 4)
                          : make_uint2(0u, 0u);
            uint2 u1 = v1 ? *(const uint2*)(g_pqh + (size_t)src1 * 80 + gl * 4)
                          : make_uint2(0u, 0u);
            float2 a0 = __half22float2(*(const __half2*)&u0.x);
            float2 b0 = __half22float2(*(const __half2*)&u0.y);
            float2 a1 = __half22float2(*(const __half2*)&u1.x);
            float2 b1 = __half22float2(*(const __half2*)&u1.y);
            acc[0] += a0.x + a1.x;
            acc[1] += a0.y + a1.y;
            acc[2] += b0.x + b1.x;
            acc[3] += b0.y + b1.y;
        }
    }

    // combine the 3 lane groups: lane<10 pulls from lane+10, lane+20
#pragma unroll
    for (int k = 0; k < 4; k++) {
        float t1 = __shfl_sync(0xffffffffu, acc[k], (lane + 10) & 31);
        float t2 = __shfl_sync(0xffffffffu, acc[k], (lane + 20) & 31);
        acc[k] += t1 + t2;           // valid for lane < 10
    }

    float inv = 1.0f / fmaxf((float)(re - rs), 1.0f);
    float v0f, v1f, v2f, v3f;
    if (lane < 10) {
        uint2 uq = *(const uint2*)(g_pqh + (size_t)warp * 80 + 40 + gl * 4);
        float2 qa = __half22float2(*(const __half2*)&uq.x);
        float2 qb = __half22float2(*(const __half2*)&uq.y);
        float4 bbv = *(const float4*)(b2 + gl * 4);
        v0f = acc[0] * inv + bbv.x + qa.x;
        v1f = acc[1] * inv + bbv.y + qa.y;
        v2f = acc[2] * inv + bbv.z + qb.x;
        v3f = acc[3] * inv + bbv.w + qb.y;
    } else {
        v0f = v1f = v2f = v3f = -INFINITY;
    }

    float mx = fmaxf(fmaxf(v0f, v1f), fmaxf(v2f, v3f));
#pragma unroll
    for (int o = 16; o; o >>= 1) mx = fmaxf(mx, __shfl_xor_sync(0xffffffffu, mx, o));
    float se = 0.f;
    if (lane < 10)
        se = expf(v0f - mx) + expf(v1f - mx) + expf(v2f - mx) + expf(v3f - mx);
#pragma unroll
    for (int o = 16; o; o >>= 1) se += __shfl_xor_sync(0xffffffffu, se, o);
    float lse = logf(se);

    if (lane < 10) {
        float4 o4 = make_float4(v0f - mx - lse, v1f - mx - lse,
                                v2f - mx - lse, v3f - mx - lse);
        *(float4*)(out + (size_t)warp * 40 + gl * 4) = o4;
    }
}

// -------------------- launch --------------------

extern "C" void kernel_launch(void* const* d_in, const int* in_sizes, int n_in,
                              void* d_out, int out_size) {
    const float* x       = (const float*)d_in[0];
    const void*  ei      = d_in[1];
    const float* Wl1     = (const float*)d_in[2];
    const float* b1      = (const float*)d_in[3];
    const float* Wr1     = (const float*)d_in[4];
    const float* Wl2     = (const float*)d_in[5];
    const float* b2      = (const float*)d_in[6];
    const float* Wr2     = (const float*)d_in[7];
    float* out           = (float*)d_out;

    cudaFuncSetAttribute(k_gemm1, cudaFuncAttributeMaxDynamicSharedMemorySize, GEMM1_SMEM);
    cudaFuncSetAttribute(k_aggr_gemm2, cudaFuncAttributeMaxDynamicSharedMemorySize, FUSED_SMEM);

    // side stream + fork/join events (created once; deterministic work per call)
    static cudaStream_t s2 = nullptr;
    static cudaEvent_t ev_fork = nullptr, ev_join = nullptr;
    if (!s2) {
        cudaStreamCreateWithFlags(&s2, cudaStreamNonBlocking);
        cudaEventCreateWithFlags(&ev_fork, cudaEventDisableTiming);
        cudaEventCreateWithFlags(&ev_join, cudaEventDisableTiming);
    }

    k_prep_w<<<1, 1024>>>(Wl1, Wr1, Wl2, Wr2);

    // fork: gemm1 depends only on x + prep_w — run it alongside the CSR build
    cudaEventRecord(ev_fork, 0);
    cudaStreamWaitEvent(s2, ev_fork, 0);
    k_gemm1<<<N_PAD / 128, 512, GEMM1_SMEM, s2>>>(x);
    cudaEventRecord(ev_join, s2);

    // main stream: CSR build chain (zero2 also does the dtype detect)
    k_zero2<<<(N_NODES + 255) / 256, 256>>>((const int*)ei);
    k_count<<<2048, 256>>>(ei);
    k_scan1<<<NB_SCAN, 1024>>>();
    k_scan2<<<1, 128>>>();
    k_scan3<<<NB_SCAN, 1024>>>();
    k_fill<<<2048, 256>>>(ei);

    // join: fused aggregation+gemm2 needs both CSR and y1/yr
    cudaStreamWaitEvent(0, ev_join, 0);
    k_aggr_gemm2<<<N_PAD / 128, 512, FUSED_SMEM>>>(b1);
    k_final<<<(N_NODES * 32 + 255) / 256, 256>>>(b2, out);
}

// round 13
// speedup vs baseline: 1.1247x; 1.0931x over previous
#include <cuda_runtime.h>
#include <cuda_bf16.h>
#include <cuda_fp16.h>
#include <mma.h>
#include <math.h>
#include <cstdint>

using namespace nvcuda;

#define N_NODES 100000
#define N_EDGES 1600000
#define N_PAD 100096                          // 782*128
#define N_TILES 782
#define NB_SCAN ((N_NODES + 1023) / 1024)     // 98

#define TS 136                                // smem A/W tile stride (bf16 elems)
#define T2S 80                                // smem W2 tile stride (160B rows)
#define TILE_ELEMS (128 * TS)

// gemm1 smem: AH, AL, WLH, WLL, WRH, WRL  (6 x 128 x 136 bf16)
#define GEMM1_SMEM (6 * TILE_ELEMS * 2)
// fused aggr+gemm2 smem: AH, AL (128x136 bf16) + W2H, W2L (128x80 bf16) = 108KB
#define FUSED_SMEM ((2 * 128 * TS + 2 * 128 * T2S) * 2)

// -------- scratch (static __device__ globals; no runtime alloc) ----------
__device__ int    g_is64;
__device__ int    g_degi[N_NODES];
__device__ int    g_cursor[N_NODES];
__device__ int    g_rowstart[N_NODES + 1];
__device__ int    g_bsum[NB_SCAN];
__device__ int    g_boff[NB_SCAN];
__device__ int    g_csrc[N_EDGES];
__device__ __half g_y1h[(size_t)N_PAD * 128]; // x @ Wl1  (fp16 — gathered 16x per node)
__device__ __half g_yrh[(size_t)N_PAD * 128]; // x @ Wr1  (fp16 — read once per node)
__device__ __half g_pqh[(size_t)N_PAD * 80];  // [p(40) | q(40)] per node (fp16)
// precomputed weight splits (bf16 hi/lo)
__device__ __nv_bfloat16 g_wl1h[16384], g_wl1l[16384];
__device__ __nv_bfloat16 g_wr1h[16384], g_wr1l[16384];
__device__ __nv_bfloat16 g_w2h[10240],  g_w2l[10240];   // [Wl2|Wr2] 128x80

// -------------------- zero + dtype detect (merged) --------------------
__global__ void k_zero2(const int* __restrict__ ei32) {
    int i = blockIdx.x * blockDim.x + threadIdx.x;
    if (i < N_NODES) { g_degi[i] = 0; g_cursor[i] = 0; }
    if (blockIdx.x == 0) {
        __shared__ int nz;
        if (threadIdx.x == 0) nz = 0;
        __syncthreads();
        if (ei32[2 * threadIdx.x + 1] != 0) atomicAdd(&nz, 1);
        __syncthreads();
        if (threadIdx.x == 0) g_is64 = (nz == 0) ? 1 : 0;
    }
}

__device__ __forceinline__ void split1(float v, __nv_bfloat16& h, __nv_bfloat16& l) {
    h = __float2bfloat16_rn(v);
    l = __float2bfloat16_rn(v - __bfloat162float(h));
}

__global__ __launch_bounds__(1024) void k_prep_w(
    const float* __restrict__ Wl1, const float* __restrict__ Wr1,
    const float* __restrict__ Wl2, const float* __restrict__ Wr2) {
    for (int i = threadIdx.x; i < 16384; i += 1024) {
        split1(Wl1[i], g_wl1h[i], g_wl1l[i]);
        split1(Wr1[i], g_wr1h[i], g_wr1l[i]);
    }
    for (int i = threadIdx.x; i < 10240; i += 1024) {
        int k = i / 80, j = i % 80;
        float v = (j < 40) ? Wl2[k * 40 + j] : Wr2[k * 40 + (j - 40)];
        split1(v, g_w2h[i], g_w2l[i]);
    }
}

// -------------------- CSR build (vectorized: 4 edges per thread) --------------------

__global__ void k_count(const void* __restrict__ ei) {
    int idx = blockIdx.x * blockDim.x + threadIdx.x;
    int stride = gridDim.x * blockDim.x;
    if (g_is64) {
        const longlong2* p = (const longlong2*)((const long long*)ei + N_EDGES);
        for (int i = idx; i < N_EDGES / 2; i += stride) {
            longlong2 v = p[i];
            atomicAdd(&g_degi[(int)v.x], 1);
            atomicAdd(&g_degi[(int)v.y], 1);
        }
    } else {
        const int4* p = (const int4*)((const int*)ei + N_EDGES);
        for (int i = idx; i < N_EDGES / 4; i += stride) {
            int4 v = p[i];
            atomicAdd(&g_degi[v.x], 1);
            atomicAdd(&g_degi[v.y], 1);
            atomicAdd(&g_degi[v.z], 1);
            atomicAdd(&g_degi[v.w], 1);
        }
    }
}

__global__ __launch_bounds__(1024) void k_scan1() {
    __shared__ int wsum[32];
    int i = blockIdx.x * 1024 + threadIdx.x;
    int lane = threadIdx.x & 31, wid = threadIdx.x >> 5;
    int v = (i < N_NODES) ? g_degi[i] : 0;
    int pre = v;
#pragma unroll
    for (int o = 1; o < 32; o <<= 1) {
        int t = __shfl_up_sync(0xffffffffu, pre, o);
        if (lane >= o) pre += t;
    }
    if (lane == 31) wsum[wid] = pre;
    __syncthreads();
    if (wid == 0) {
        int w = wsum[lane];
        int p = w;
#pragma unroll
        for (int o = 1; o < 32; o <<= 1) {
            int t = __shfl_up_sync(0xffffffffu, p, o);
            if (lane >= o) p += t;
        }
        wsum[lane] = p - w;
        if (lane == 31) g_bsum[blockIdx.x] = p;
    }
    __syncthreads();
    if (i < N_NODES) g_rowstart[i] = pre - v + wsum[wid];
}

__global__ void k_scan2() {
    int t = threadIdx.x;            // 128 threads
    int lane = t & 31, wid = t >> 5;
    __shared__ int ws[4];
    int v = (t < NB_SCAN) ? g_bsum[t] : 0;
    int pre = v;
#pragma unroll
    for (int o = 1; o < 32; o <<= 1) {
        int u = __shfl_up_sync(0xffffffffu, pre, o);
        if (lane >= o) pre += u;
    }
    if (lane == 31) ws[wid] = pre;
    __syncthreads();
    if (t == 0) {
        int r = 0;
#pragma unroll
        for (int k = 0; k < 4; k++) { int tmp = ws[k]; ws[k] = r; r += tmp; }
        g_rowstart[N_NODES] = N_EDGES;
    }
    __syncthreads();
    if (t < NB_SCAN) g_boff[t] = pre - v + ws[wid];
}

__global__ __launch_bounds__(1024) void k_scan3() {
    int i = blockIdx.x * 1024 + threadIdx.x;
    if (i < N_NODES) g_rowstart[i] += g_boff[blockIdx.x];
}

__global__ void k_fill(const void* __restrict__ ei) {
    int idx = blockIdx.x * blockDim.x + threadIdx.x;
    int stride = gridDim.x * blockDim.x;
    if (g_is64) {
        const longlong2* ps = (const longlong2*)ei;
        const longlong2* pd = (const longlong2*)((const long long*)ei + N_EDGES);
        for (int i = idx; i < N_EDGES / 2; i += stride) {
            longlong2 s = ps[i];
            longlong2 d = pd[i];
            int d0 = (int)d.x, d1 = (int)d.y;
            int p0 = atomicAdd(&g_cursor[d0], 1);
            g_csrc[g_rowstart[d0] + p0] = (int)s.x;
            int p1 = atomicAdd(&g_cursor[d1], 1);
            g_csrc[g_rowstart[d1] + p1] = (int)s.y;
        }
    } else {
        const int4* ps = (const int4*)ei;
        const int4* pd = (const int4*)((const int*)ei + N_EDGES);
        for (int i = idx; i < N_EDGES / 4; i += stride) {
            int4 s = ps[i];
            int4 d = pd[i];
            int p0 = atomicAdd(&g_cursor[d.x], 1); g_csrc[g_rowstart[d.x] + p0] = s.x;
            int p1 = atomicAdd(&g_cursor[d.y], 1); g_csrc[g_rowstart[d.y] + p1] = s.y;
            int p2 = atomicAdd(&g_cursor[d.z], 1); g_csrc[g_rowstart[d.z] + p2] = s.z;
            int p3 = atomicAdd(&g_cursor[d.w], 1); g_csrc[g_rowstart[d.w] + p3] = s.w;
        }
    }
}

// ============ helpers for wmma GEMMs ============

// convert 4 fp32 -> hi/lo packed bf16x2 pairs
__device__ __forceinline__ void split4(float4 v, uint2& hi, uint2& lo) {
    __nv_bfloat162 h01 = __floats2bfloat162_rn(v.x, v.y);
    __nv_bfloat162 h23 = __floats2bfloat162_rn(v.z, v.w);
    float r0 = v.x - __low2float(h01),  r1 = v.y - __high2float(h01);
    float r2 = v.z - __low2float(h23),  r3 = v.w - __high2float(h23);
    __nv_bfloat162 l01 = __floats2bfloat162_rn(r0, r1);
    __nv_bfloat162 l23 = __floats2bfloat162_rn(r2, r3);
    hi = make_uint2(*(uint32_t*)&h01, *(uint32_t*)&h23);
    lo = make_uint2(*(uint32_t*)&l01, *(uint32_t*)&l23);
}

// convert 128x128 fp32 (row stride 128, rows clamped) into hi/lo smem tiles
template <int NTHREADS>
__device__ __forceinline__ void conv_tile(const float* __restrict__ src, int row0,
                                          __nv_bfloat16* H, __nv_bfloat16* L, int tid) {
    for (int g = tid; g < 4096; g += NTHREADS) {
        int row = g >> 5, c4 = g & 31;
        int r = row0 + row;
        if (r >= N_NODES) r = N_NODES - 1;
        float4 v = ((const float4*)(src + (size_t)r * 128))[c4];
        uint2 hi, lo;
        split4(v, hi, lo);
        *(uint2*)(H + row * TS + c4 * 4) = hi;
        *(uint2*)(L + row * TS + c4 * 4) = lo;
    }
}

// ============ GEMM 1 (persistent): y1 = x@Wl1, yr = x@Wr1, both fp16 out ============
// 148 CTAs x 512 threads; each CTA loops over tiles, weights loaded to smem ONCE.
// Warps 0-7 -> y1 (weights WL), warps 8-15 -> yr (weights WR); 32x64 out each.

__global__ __launch_bounds__(512) void k_gemm1(const float* __restrict__ x) {
    extern __shared__ __nv_bfloat16 sm[];
    __nv_bfloat16* AH  = sm;
    __nv_bfloat16* AL  = sm + TILE_ELEMS;
    __nv_bfloat16* WH0 = sm + 2 * TILE_ELEMS;  // WL hi
    __nv_bfloat16* WL0 = sm + 3 * TILE_ELEMS;  // WL lo
    __nv_bfloat16* WH1 = sm + 4 * TILE_ELEMS;  // WR hi
    __nv_bfloat16* WL1 = sm + 5 * TILE_ELEMS;  // WR lo

    int tid = threadIdx.x;
    int wid = tid >> 5, lane = tid & 31;

    // copy precomputed weight splits into padded smem ONCE (one uint4 = 8 bf16)
    {
        const __nv_bfloat16* srcs[4] = {g_wl1h, g_wl1l, g_wr1h, g_wr1l};
        __nv_bfloat16* dsts[4] = {WH0, WL0, WH1, WL1};
#pragma unroll
        for (int tgt = 0; tgt < 4; tgt++) {
            const uint4* s = (const uint4*)srcs[tgt];
            for (int g = tid; g < 2048; g += 512) {   // 128 rows x 16 uint4
                int row = g >> 4, c = g & 15;
                *(uint4*)(dsts[tgt] + row * TS + c * 8) = s[row * 16 + c];
            }
        }
    }

    int out_sel = wid >> 3;          // 0: y1, 1: yr
    int w = wid & 7;
    int wm = w & 3;                  // rows wm*32
    int wn = w >> 2;                 // cols wn*64
    const __nv_bfloat16* WH = out_sel ? WH1 : WH0;
    const __nv_bfloat16* WL = out_sel ? WL1 : WL0;
    __half* dstbase = out_sel ? g_yrh : g_y1h;
    // per-warp fp32 staging region inside AH/AL space: 16 warps x 1024 floats = 64KB
    float* eb = (float*)sm + (size_t)wid * 1024;

    for (int tile = blockIdx.x; tile < N_TILES; tile += gridDim.x) {
        int node0 = tile * 128;
        conv_tile<512>(x, node0, AH, AL, tid);
        __syncthreads();   // A ready (and, first iter, weights ready)

        wmma::fragment<wmma::accumulator, 16, 16, 16, float> C[2][4];
#pragma unroll
        for (int i = 0; i < 2; i++)
#pragma unroll
            for (int j = 0; j < 4; j++) wmma::fill_fragment(C[i][j], 0.0f);

#pragma unroll
        for (int k0 = 0; k0 < 8; k0++) {
            wmma::fragment<wmma::matrix_a, 16, 16, 16, __nv_bfloat16, wmma::row_major> ah[2], al[2];
#pragma unroll
            for (int i = 0; i < 2; i++) {
                wmma::load_matrix_sync(ah[i], AH + (wm * 32 + i * 16) * TS + k0 * 16, TS);
                wmma::load_matrix_sync(al[i], AL + (wm * 32 + i * 16) * TS + k0 * 16, TS);
            }
#pragma unroll
            for (int j = 0; j < 4; j++) {
                wmma::fragment<wmma::matrix_b, 16, 16, 16, __nv_bfloat16, wmma::row_major> bh, bl;
                wmma::load_matrix_sync(bh, WH + (k0 * 16) * TS + wn * 64 + j * 16, TS);
                wmma::load_matrix_sync(bl, WL + (k0 * 16) * TS + wn * 64 + j * 16, TS);
#pragma unroll
                for (int i = 0; i < 2; i++) {
                    wmma::mma_sync(C[i][j], ah[i], bh, C[i][j]);
                    wmma::mma_sync(C[i][j], al[i], bh, C[i][j]);
                    wmma::mma_sync(C[i][j], ah[i], bl, C[i][j]);
                }
            }
        }
        __syncthreads();   // all warps done reading AH/AL -> reuse as staging

        // epilogue: per warp stage 16x64 fp32 at a time, convert to fp16, store
#pragma unroll
        for (int i = 0; i < 2; i++) {
#pragma unroll
            for (int j = 0; j < 4; j++)
                wmma::store_matrix_sync(eb + j * 16, C[i][j], 64, wmma::mem_row_major);
            __syncwarp();
            for (int e = lane; e < 512; e += 32) {    // 16 rows x 32 half2
                int r = e >> 5, c2 = e & 31;
                float2 v = ((const float2*)eb)[e];
                __half2 hv = __floats2half2_rn(v.x, v.y);
                *(__half2*)(dstbase + (size_t)(node0 + wm * 32 + i * 16 + r) * 128
                            + wn * 64 + c2 * 2) = hv;
            }
            __syncwarp();
        }
        __syncthreads();   // staging reads done before next tile's conv overwrites
    }
}

// ====== FUSED: h = relu(mean-gather(y1) + yr + b1)  ->  pq = h @ [Wl2|Wr2] ======
// 512 threads per CTA, 2 CTAs/SM (smem 108KB). 128 nodes per CTA.

__global__ __launch_bounds__(512, 2) void k_aggr_gemm2(const float* __restrict__ b1) {
    extern __shared__ __nv_bfloat16 sm[];
    __nv_bfloat16* AH  = sm;
    __nv_bfloat16* AL  = sm + TILE_ELEMS;
    __nv_bfloat16* W2H = sm + 2 * TILE_ELEMS;
    __nv_bfloat16* W2L = sm + 2 * TILE_ELEMS + 128 * T2S;

    int tid = threadIdx.x;
    int wid = tid >> 5, lane = tid & 31;
    int node0 = blockIdx.x * 128;

    // copy W2 splits (128x80) into smem (T2S=80 -> 160B rows, benign 2-way)
    {
        const uint4* sh = (const uint4*)g_w2h;
        const uint4* sl = (const uint4*)g_w2l;
        for (int g = tid; g < 1280; g += 512) {   // 128 rows x 10 uint4
            int row = g / 10, c = g % 10;
            *(uint4*)(W2H + row * T2S + c * 8) = sh[row * 10 + c];
            *(uint4*)(W2L + row * T2S + c * 8) = sl[row * 10 + c];
        }
    }

    // ---- Phase A: gather (y1 fp16) + relu, split into smem ----
    float4 bb = *(const float4*)(b1 + lane * 4);
#pragma unroll
    for (int i = 0; i < 8; i++) {
        int nl = wid * 8 + i;
        int node = node0 + nl;
        float4 h4 = make_float4(0.f, 0.f, 0.f, 0.f);
        if (node < N_NODES) {
            int rs = g_rowstart[node], re = g_rowstart[node + 1];
            float4 acc = make_float4(0.f, 0.f, 0.f, 0.f);
            for (int i0 = rs; i0 < re; i0 += 32) {
                int nv = min(32, re - i0);
                int s = (lane < nv) ? g_csrc[i0 + lane] : 0;
                int j = 0;
                for (; j + 8 <= nv; j += 8) {
                    uint2 u[8];
#pragma unroll
                    for (int t = 0; t < 8; t++) {
                        int sj = __shfl_sync(0xffffffffu, s, j + t);
                        u[t] = *(const uint2*)(g_y1h + (size_t)sj * 128 + lane * 4);
                    }
#pragma unroll
                    for (int t = 0; t < 8; t++) {
                        float2 a = __half22float2(*(const __half2*)&u[t].x);
                        float2 b = __half22float2(*(const __half2*)&u[t].y);
                        acc.x += a.x; acc.y += a.y; acc.z += b.x; acc.w += b.y;
                    }
                }
                for (; j < nv; j++) {
                    int sj = __shfl_sync(0xffffffffu, s, j);
                    uint2 u = *(const uint2*)(g_y1h + (size_t)sj * 128 + lane * 4);
                    float2 a = __half22float2(*(const __half2*)&u.x);
                    float2 b = __half22float2(*(const __half2*)&u.y);
                    acc.x += a.x; acc.y += a.y; acc.z += b.x; acc.w += b.y;
                }
            }
            float inv = 1.0f / fmaxf((float)(re - rs), 1.0f);
            uint2 uyr = *(const uint2*)(g_yrh + (size_t)node * 128 + lane * 4);
            float2 ya = __half22float2(*(const __half2*)&uyr.x);
            float2 yb = __half22float2(*(const __half2*)&uyr.y);
            h4.x = fmaxf(acc.x * inv + ya.x + bb.x, 0.f);
            h4.y = fmaxf(acc.y * inv + ya.y + bb.y, 0.f);
            h4.z = fmaxf(acc.z * inv + yb.x + bb.z, 0.f);
            h4.w = fmaxf(acc.w * inv + yb.y + bb.w, 0.f);
        }
        uint2 hi, lo;
        split4(h4, hi, lo);
        *(uint2*)(AH + nl * TS + lane * 4) = hi;
        *(uint2*)(AL + nl * TS + lane * 4) = lo;
    }
    __syncthreads();

    // ---- Phase B: wmma gemm2 ----
    int rblk = wid & 7;                 // rows rblk*16 .. +15
    int j0   = (wid < 8) ? 0 : 3;       // col frags {0,1,2} or {3,4}
    int nj   = (wid < 8) ? 3 : 2;

    wmma::fragment<wmma::accumulator, 16, 16, 16, float> C[3];
#pragma unroll
    for (int j = 0; j < 3; j++) wmma::fill_fragment(C[j], 0.0f);

#pragma unroll
    for (int k0 = 0; k0 < 8; k0++) {
        wmma::fragment<wmma::matrix_a, 16, 16, 16, __nv_bfloat16, wmma::row_major> ah, al;
        wmma::load_matrix_sync(ah, AH + (rblk * 16) * TS + k0 * 16, TS);
        wmma::load_matrix_sync(al, AL + (rblk * 16) * TS + k0 * 16, TS);
        for (int j = 0; j < nj; j++) {
            wmma::fragment<wmma::matrix_b, 16, 16, 16, __nv_bfloat16, wmma::row_major> bh, bl;
            wmma::load_matrix_sync(bh, W2H + (k0 * 16) * T2S + (j0 + j) * 16, T2S);
            wmma::load_matrix_sync(bl, W2L + (k0 * 16) * T2S + (j0 + j) * 16, T2S);
            wmma::mma_sync(C[j], ah, bh, C[j]);
            wmma::mma_sync(C[j], al, bh, C[j]);
            wmma::mma_sync(C[j], ah, bl, C[j]);
        }
    }
    __syncthreads();   // all mma reads of AH/AL done -> reuse as fp32 staging

    // ---- epilogue: stage fp32 pq (128x80) in smem, convert to fp16 ----
    float* stage = (float*)sm;          // 128*80*4 = 40960 B (fits in AH+AL region)
    for (int j = 0; j < nj; j++)
        wmma::store_matrix_sync(stage + (rblk * 16) * 80 + (j0 + j) * 16, C[j],
                                80, wmma::mem_row_major);
    __syncthreads();
    for (int g = tid; g < 5120; g += 512) {   // 128 rows x 40 half2
        int row = g / 40, c2 = g % 40;
        float2 v = ((const float2*)stage)[g];
        __half2 hv = __floats2half2_rn(v.x, v.y);
        *(__half2*)(g_pqh + (size_t)(node0 + row) * 80 + c2 * 2) = hv;
    }
}

// ---------- layer-2 aggregation + bias + log_softmax ----------
// warp per node; 3 lane-groups of 10 gather 3 edges per load instruction.

__global__ void k_final(const float* __restrict__ b2, float* __restrict__ out) {
    int warp = (blockIdx.x * blockDim.x + threadIdx.x) >> 5;
    if (warp >= N_NODES) return;
    int lane = threadIdx.x & 31;
    int g  = lane / 10;          // 0,1,2 (lanes 30,31 idle)
    int gl = lane % 10;
    bool active = lane < 30;
    int rs = g_rowstart[warp], re = g_rowstart[warp + 1];
    float acc[4] = {0.f, 0.f, 0.f, 0.f};

    for (int i0 = rs; i0 < re; i0 += 32) {
        int nv = min(32, re - i0);
        int s = (lane < nv) ? g_csrc[i0 + lane] : 0;
        for (int j = 0; j < nv; j += 6) {
            int e0 = j + g, e1 = j + 3 + g;
            int src0 = __shfl_sync(0xffffffffu, s, (e0 < nv) ? e0 : 0);
            int src1 = __shfl_sync(0xffffffffu, s, (e1 < nv) ? e1 : 0);
            bool v0 = active && (e0 < nv);
            bool v1 = active && (e1 < nv);
            uint2 u0 = v0 ? *(const uint2*)(g_pqh + (size_t)src0 * 80 + gl * 4)
                          : make_uint2(0u, 0u);
            uint2 u1 = v1 ? *(const uint2*)(g_pqh + (size_t)src1 * 80 + gl * 4)
                          : make_uint2(0u, 0u);
            float2 a0 = __half22float2(*(const __half2*)&u0.x);
            float2 b0 = __half22float2(*(const __half2*)&u0.y);
            float2 a1 = __half22float2(*(const __half2*)&u1.x);
            float2 b1 = __half22float2(*(const __half2*)&u1.y);
            acc[0] += a0.x + a1.x;
            acc[1] += a0.y + a1.y;
            acc[2] += b0.x + b1.x;
            acc[3] += b0.y + b1.y;
        }
    }

    // combine the 3 lane groups: lane<10 pulls from lane+10, lane+20
#pragma unroll
    for (int k = 0; k < 4; k++) {
        float t1 = __shfl_sync(0xffffffffu, acc[k], (lane + 10) & 31);
        float t2 = __shfl_sync(0xffffffffu, acc[k], (lane + 20) & 31);
        acc[k] += t1 + t2;           // valid for lane < 10
    }

    float inv = 1.0f / fmaxf((float)(re - rs), 1.0f);
    float v0f, v1f, v2f, v3f;
    if (lane < 10) {
        uint2 uq = *(const uint2*)(g_pqh + (size_t)warp * 80 + 40 + gl * 4);
        float2 qa = __half22float2(*(const __half2*)&uq.x);
        float2 qb = __half22float2(*(const __half2*)&uq.y);
        float4 bbv = *(const float4*)(b2 + gl * 4);
        v0f = acc[0] * inv + bbv.x + qa.x;
        v1f = acc[1] * inv + bbv.y + qa.y;
        v2f = acc[2] * inv + bbv.z + qb.x;
        v3f = acc[3] * inv + bbv.w + qb.y;
    } else {
        v0f = v1f = v2f = v3f = -INFINITY;
    }

    float mx = fmaxf(fmaxf(v0f, v1f), fmaxf(v2f, v3f));
#pragma unroll
    for (int o = 16; o; o >>= 1) mx = fmaxf(mx, __shfl_xor_sync(0xffffffffu, mx, o));
    float se = 0.f;
    if (lane < 10)
        se = expf(v0f - mx) + expf(v1f - mx) + expf(v2f - mx) + expf(v3f - mx);
#pragma unroll
    for (int o = 16; o; o >>= 1) se += __shfl_xor_sync(0xffffffffu, se, o);
    float lse = logf(se);

    if (lane < 10) {
        float4 o4 = make_float4(v0f - mx - lse, v1f - mx - lse,
                                v2f - mx - lse, v3f - mx - lse);
        *(float4*)(out + (size_t)warp * 40 + gl * 4) = o4;
    }
}

// -------------------- launch --------------------

extern "C" void kernel_launch(void* const* d_in, const int* in_sizes, int n_in,
                              void* d_out, int out_size) {
    const float* x       = (const float*)d_in[0];
    const void*  ei      = d_in[1];
    const float* Wl1     = (const float*)d_in[2];
    const float* b1      = (const float*)d_in[3];
    const float* Wr1     = (const float*)d_in[4];
    const float* Wl2     = (const float*)d_in[5];
    const float* b2      = (const float*)d_in[6];
    const float* Wr2     = (const float*)d_in[7];
    float* out           = (float*)d_out;

    cudaFuncSetAttribute(k_gemm1, cudaFuncAttributeMaxDynamicSharedMemorySize, GEMM1_SMEM);
    cudaFuncSetAttribute(k_aggr_gemm2, cudaFuncAttributeMaxDynamicSharedMemorySize, FUSED_SMEM);

    // side stream + fork/join events (created once; deterministic work per call)
    static cudaStream_t s2 = nullptr;
    static cudaEvent_t ev_fork = nullptr, ev_join = nullptr;
    if (!s2) {
        cudaStreamCreateWithFlags(&s2, cudaStreamNonBlocking);
        cudaEventCreateWithFlags(&ev_fork, cudaEventDisableTiming);
        cudaEventCreateWithFlags(&ev_join, cudaEventDisableTiming);
    }

    k_prep_w<<<1, 1024>>>(Wl1, Wr1, Wl2, Wr2);

    // fork: gemm1 depends only on x + prep_w — run it alongside the CSR build
    cudaEventRecord(ev_fork, 0);
    cudaStreamWaitEvent(s2, ev_fork, 0);
    k_gemm1<<<148, 512, GEMM1_SMEM, s2>>>(x);
    cudaEventRecord(ev_join, s2);

    // main stream: CSR build chain (zero2 also does the dtype detect)
    k_zero2<<<(N_NODES + 255) / 256, 256>>>((const int*)ei);
    k_count<<<1024, 256>>>(ei);
    k_scan1<<<NB_SCAN, 1024>>>();
    k_scan2<<<1, 128>>>();
    k_scan3<<<NB_SCAN, 1024>>>();
    k_fill<<<1024, 256>>>(ei);

    // join: fused aggregation+gemm2 needs both CSR and y1/yr
    cudaStreamWaitEvent(0, ev_join, 0);
    k_aggr_gemm2<<<N_PAD / 128, 512, FUSED_SMEM>>>(b1);
    k_final<<<(N_NODES * 32 + 255) / 256, 256>>>(b2, out);
}

// round 14
// speedup vs baseline: 1.4122x; 1.2556x over previous
#include <cuda_runtime.h>
#include <cuda_fp16.h>
#include <mma.h>
#include <math.h>
#include <cstdint>

using namespace nvcuda;

#define N_NODES 100000
#define N_EDGES 1600000
#define N_PAD 100096                          // 782*128
#define N_TILES 782
#define NB_SCAN ((N_NODES + 1023) / 1024)     // 98

#define TS 136                                // smem A/W tile stride (fp16 elems)
#define T2S 80                                // smem W2 tile stride (160B rows)
#define TILE_ELEMS (128 * TS)                 // 17408

// gemm1 smem: AH, WH0, WH1 (3 x 128x136 fp16) + 64KB fp32 staging
#define GEMM1_SMEM (3 * TILE_ELEMS * 2 + 16 * 1024 * 4)
// fused smem: AH (128x136 fp16) + W2H (128x80 fp16)
#define FUSED_SMEM ((TILE_ELEMS + 128 * T2S) * 2)

// -------- scratch (static __device__ globals; no runtime alloc) ----------
__device__ int    g_is64;
__device__ int    g_degi[N_NODES];
__device__ int    g_cursor[N_NODES];
__device__ int    g_rowstart[N_NODES + 1];
__device__ int    g_bsum[NB_SCAN];
__device__ int    g_boff[NB_SCAN];
__device__ int    g_csrc[N_EDGES];
__device__ __half g_y1h[(size_t)N_PAD * 128]; // x @ Wl1  (fp16)
__device__ __half g_yrh[(size_t)N_PAD * 128]; // x @ Wr1  (fp16)
__device__ __half g_pqh[(size_t)N_PAD * 80];  // [p(40) | q(40)] per node (fp16)
// precomputed fp16 weights
__device__ __half g_wl1h[16384];
__device__ __half g_wr1h[16384];
__device__ __half g_w2h[10240];               // [Wl2|Wr2] 128x80

// -------------------- zero + dtype detect (merged) --------------------
__global__ void k_zero2(const int* __restrict__ ei32) {
    int i = blockIdx.x * blockDim.x + threadIdx.x;
    if (i < N_NODES) { g_degi[i] = 0; g_cursor[i] = 0; }
    if (blockIdx.x == 0) {
        __shared__ int nz;
        if (threadIdx.x == 0) nz = 0;
        __syncthreads();
        if (ei32[2 * threadIdx.x + 1] != 0) atomicAdd(&nz, 1);
        __syncthreads();
        if (threadIdx.x == 0) g_is64 = (nz == 0) ? 1 : 0;
    }
}

__global__ __launch_bounds__(1024) void k_prep_w(
    const float* __restrict__ Wl1, const float* __restrict__ Wr1,
    const float* __restrict__ Wl2, const float* __restrict__ Wr2) {
    for (int i = threadIdx.x; i < 16384; i += 1024) {
        g_wl1h[i] = __float2half_rn(Wl1[i]);
        g_wr1h[i] = __float2half_rn(Wr1[i]);
    }
    for (int i = threadIdx.x; i < 10240; i += 1024) {
        int k = i / 80, j = i % 80;
        float v = (j < 40) ? Wl2[k * 40 + j] : Wr2[k * 40 + (j - 40)];
        g_w2h[i] = __float2half_rn(v);
    }
}

// -------------------- CSR build (vectorized: 4 edges per thread) --------------------

__global__ void k_count(const void* __restrict__ ei) {
    int idx = blockIdx.x * blockDim.x + threadIdx.x;
    int stride = gridDim.x * blockDim.x;
    if (g_is64) {
        const longlong2* p = (const longlong2*)((const long long*)ei + N_EDGES);
        for (int i = idx; i < N_EDGES / 2; i += stride) {
            longlong2 v = p[i];
            atomicAdd(&g_degi[(int)v.x], 1);
            atomicAdd(&g_degi[(int)v.y], 1);
        }
    } else {
        const int4* p = (const int4*)((const int*)ei + N_EDGES);
        for (int i = idx; i < N_EDGES / 4; i += stride) {
            int4 v = p[i];
            atomicAdd(&g_degi[v.x], 1);
            atomicAdd(&g_degi[v.y], 1);
            atomicAdd(&g_degi[v.z], 1);
            atomicAdd(&g_degi[v.w], 1);
        }
    }
}

__global__ __launch_bounds__(1024) void k_scan1() {
    __shared__ int wsum[32];
    int i = blockIdx.x * 1024 + threadIdx.x;
    int lane = threadIdx.x & 31, wid = threadIdx.x >> 5;
    int v = (i < N_NODES) ? g_degi[i] : 0;
    int pre = v;
#pragma unroll
    for (int o = 1; o < 32; o <<= 1) {
        int t = __shfl_up_sync(0xffffffffu, pre, o);
        if (lane >= o) pre += t;
    }
    if (lane == 31) wsum[wid] = pre;
    __syncthreads();
    if (wid == 0) {
        int w = wsum[lane];
        int p = w;
#pragma unroll
        for (int o = 1; o < 32; o <<= 1) {
            int t = __shfl_up_sync(0xffffffffu, p, o);
            if (lane >= o) p += t;
        }
        wsum[lane] = p - w;
        if (lane == 31) g_bsum[blockIdx.x] = p;
    }
    __syncthreads();
    if (i < N_NODES) g_rowstart[i] = pre - v + wsum[wid];
}

__global__ void k_scan2() {
    int t = threadIdx.x;            // 128 threads
    int lane = t & 31, wid = t >> 5;
    __shared__ int ws[4];
    int v = (t < NB_SCAN) ? g_bsum[t] : 0;
    int pre = v;
#pragma unroll
    for (int o = 1; o < 32; o <<= 1) {
        int u = __shfl_up_sync(0xffffffffu, pre, o);
        if (lane >= o) pre += u;
    }
    if (lane == 31) ws[wid] = pre;
    __syncthreads();
    if (t == 0) {
        int r = 0;
#pragma unroll
        for (int k = 0; k < 4; k++) { int tmp = ws[k]; ws[k] = r; r += tmp; }
        g_rowstart[N_NODES] = N_EDGES;
    }
    __syncthreads();
    if (t < NB_SCAN) g_boff[t] = pre - v + ws[wid];
}

__global__ __launch_bounds__(1024) void k_scan3() {
    int i = blockIdx.x * 1024 + threadIdx.x;
    if (i < N_NODES) g_rowstart[i] += g_boff[blockIdx.x];
}

__global__ void k_fill(const void* __restrict__ ei) {
    int idx = blockIdx.x * blockDim.x + threadIdx.x;
    int stride = gridDim.x * blockDim.x;
    if (g_is64) {
        const longlong2* ps = (const longlong2*)ei;
        const longlong2* pd = (const longlong2*)((const long long*)ei + N_EDGES);
        for (int i = idx; i < N_EDGES / 2; i += stride) {
            longlong2 s = ps[i];
            longlong2 d = pd[i];
            int d0 = (int)d.x, d1 = (int)d.y;
            int p0 = atomicAdd(&g_cursor[d0], 1);
            g_csrc[g_rowstart[d0] + p0] = (int)s.x;
            int p1 = atomicAdd(&g_cursor[d1], 1);
            g_csrc[g_rowstart[d1] + p1] = (int)s.y;
        }
    } else {
        const int4* ps = (const int4*)ei;
        const int4* pd = (const int4*)((const int*)ei + N_EDGES);
        for (int i = idx; i < N_EDGES / 4; i += stride) {
            int4 s = ps[i];
            int4 d = pd[i];
            int p0 = atomicAdd(&g_cursor[d.x], 1); g_csrc[g_rowstart[d.x] + p0] = s.x;
            int p1 = atomicAdd(&g_cursor[d.y], 1); g_csrc[g_rowstart[d.y] + p1] = s.y;
            int p2 = atomicAdd(&g_cursor[d.z], 1); g_csrc[g_rowstart[d.z] + p2] = s.z;
            int p3 = atomicAdd(&g_cursor[d.w], 1); g_csrc[g_rowstart[d.w] + p3] = s.w;
        }
    }
}

// ============ helpers ============

// convert 128x128 fp32 (row stride 128, rows clamped) into a single fp16 tile
template <int NTHREADS>
__device__ __forceinline__ void conv_tile_h(const float* __restrict__ src, int row0,
                                            __half* H, int tid) {
    for (int g = tid; g < 4096; g += NTHREADS) {
        int row = g >> 5, c4 = g & 31;
        int r = row0 + row;
        if (r >= N_NODES) r = N_NODES - 1;
        float4 v = ((const float4*)(src + (size_t)r * 128))[c4];
        __half2 h0 = __floats2half2_rn(v.x, v.y);
        __half2 h1 = __floats2half2_rn(v.z, v.w);
        *(uint2*)(H + row * TS + c4 * 4) = make_uint2(*(uint32_t*)&h0, *(uint32_t*)&h1);
    }
}

// ============ GEMM 1 (persistent, fp16 single-pass): y1 = x@Wl1, yr = x@Wr1 ============
// 148 CTAs x 512 threads; weights in smem once. Warps 0-7 -> y1, 8-15 -> yr.

__global__ __launch_bounds__(512) void k_gemm1(const float* __restrict__ x) {
    extern __shared__ __half sm[];
    __half* AH  = sm;
    __half* WH0 = sm + TILE_ELEMS;
    __half* WH1 = sm + 2 * TILE_ELEMS;
    float* staging = (float*)(sm + 3 * TILE_ELEMS);

    int tid = threadIdx.x;
    int wid = tid >> 5, lane = tid & 31;

    // copy fp16 weights into padded smem ONCE (one uint4 = 8 halves)
    {
        const __half* srcs[2] = {g_wl1h, g_wr1h};
        __half* dsts[2] = {WH0, WH1};
#pragma unroll
        for (int tgt = 0; tgt < 2; tgt++) {
            const uint4* s = (const uint4*)srcs[tgt];
            for (int g = tid; g < 2048; g += 512) {   // 128 rows x 16 uint4
                int row = g >> 4, c = g & 15;
                *(uint4*)(dsts[tgt] + row * TS + c * 8) = s[row * 16 + c];
            }
        }
    }

    int out_sel = wid >> 3;          // 0: y1, 1: yr
    int w = wid & 7;
    int wm = w & 3;                  // rows wm*32
    int wn = w >> 2;                 // cols wn*64
    const __half* WH = out_sel ? WH1 : WH0;
    __half* dstbase = out_sel ? g_yrh : g_y1h;
    float* eb = staging + (size_t)wid * 1024;   // 16x64 fp32 per warp

    for (int tile = blockIdx.x; tile < N_TILES; tile += gridDim.x) {
        int node0 = tile * 128;
        conv_tile_h<512>(x, node0, AH, tid);
        __syncthreads();

        wmma::fragment<wmma::accumulator, 16, 16, 16, float> C[2][4];
#pragma unroll
        for (int i = 0; i < 2; i++)
#pragma unroll
            for (int j = 0; j < 4; j++) wmma::fill_fragment(C[i][j], 0.0f);

#pragma unroll
        for (int k0 = 0; k0 < 8; k0++) {
            wmma::fragment<wmma::matrix_a, 16, 16, 16, __half, wmma::row_major> ah[2];
#pragma unroll
            for (int i = 0; i < 2; i++)
                wmma::load_matrix_sync(ah[i], AH + (wm * 32 + i * 16) * TS + k0 * 16, TS);
#pragma unroll
            for (int j = 0; j < 4; j++) {
                wmma::fragment<wmma::matrix_b, 16, 16, 16, __half, wmma::row_major> bh;
                wmma::load_matrix_sync(bh, WH + (k0 * 16) * TS + wn * 64 + j * 16, TS);
#pragma unroll
                for (int i = 0; i < 2; i++)
                    wmma::mma_sync(C[i][j], ah[i], bh, C[i][j]);
            }
        }

        // epilogue: per warp stage 16x64 fp32 at a time, convert to fp16, store
#pragma unroll
        for (int i = 0; i < 2; i++) {
#pragma unroll
            for (int j = 0; j < 4; j++)
                wmma::store_matrix_sync(eb + j * 16, C[i][j], 64, wmma::mem_row_major);
            __syncwarp();
            for (int e = lane; e < 512; e += 32) {    // 16 rows x 32 half2
                int r = e >> 5, c2 = e & 31;
                float2 v = ((const float2*)eb)[e];
                __half2 hv = __floats2half2_rn(v.x, v.y);
                *(__half2*)(dstbase + (size_t)(node0 + wm * 32 + i * 16 + r) * 128
                            + wn * 64 + c2 * 2) = hv;
            }
            __syncwarp();
        }
        __syncthreads();   // A reads done before next tile's conv overwrites
    }
}

// ====== FUSED: h = relu(mean-gather(y1) + yr + b1)  ->  pq = h @ [Wl2|Wr2] ======
// 512 threads per CTA. 128 nodes per CTA. fp16 single-pass gemm2.

__global__ __launch_bounds__(512) void k_aggr_gemm2(const float* __restrict__ b1) {
    extern __shared__ __half sm[];
    __half* AH  = sm;
    __half* W2H = sm + TILE_ELEMS;

    int tid = threadIdx.x;
    int wid = tid >> 5, lane = tid & 31;
    int node0 = blockIdx.x * 128;

    // copy W2 fp16 (128x80) into smem
    {
        const uint4* sh = (const uint4*)g_w2h;
        for (int g = tid; g < 1280; g += 512) {   // 128 rows x 10 uint4
            int row = g / 10, c = g % 10;
            *(uint4*)(W2H + row * T2S + c * 8) = sh[row * 10 + c];
        }
    }

    // ---- Phase A: gather (y1 fp16) + relu, fp16 into smem ----
    float4 bb = *(const float4*)(b1 + lane * 4);
#pragma unroll
    for (int i = 0; i < 8; i++) {
        int nl = wid * 8 + i;
        int node = node0 + nl;
        float4 h4 = make_float4(0.f, 0.f, 0.f, 0.f);
        if (node < N_NODES) {
            int rs = g_rowstart[node], re = g_rowstart[node + 1];
            float4 acc = make_float4(0.f, 0.f, 0.f, 0.f);
            for (int i0 = rs; i0 < re; i0 += 32) {
                int nv = min(32, re - i0);
                int s = (lane < nv) ? g_csrc[i0 + lane] : 0;
                int j = 0;
                for (; j + 8 <= nv; j += 8) {
                    uint2 u[8];
#pragma unroll
                    for (int t = 0; t < 8; t++) {
                        int sj = __shfl_sync(0xffffffffu, s, j + t);
                        u[t] = *(const uint2*)(g_y1h + (size_t)sj * 128 + lane * 4);
                    }
#pragma unroll
                    for (int t = 0; t < 8; t++) {
                        float2 a = __half22float2(*(const __half2*)&u[t].x);
                        float2 b = __half22float2(*(const __half2*)&u[t].y);
                        acc.x += a.x; acc.y += a.y; acc.z += b.x; acc.w += b.y;
                    }
                }
                for (; j < nv; j++) {
                    int sj = __shfl_sync(0xffffffffu, s, j);
                    uint2 u = *(const uint2*)(g_y1h + (size_t)sj * 128 + lane * 4);
                    float2 a = __half22float2(*(const __half2*)&u.x);
                    float2 b = __half22float2(*(const __half2*)&u.y);
                    acc.x += a.x; acc.y += a.y; acc.z += b.x; acc.w += b.y;
                }
            }
            float inv = 1.0f / fmaxf((float)(re - rs), 1.0f);
            uint2 uyr = *(const uint2*)(g_yrh + (size_t)node * 128 + lane * 4);
            float2 ya = __half22float2(*(const __half2*)&uyr.x);
            float2 yb = __half22float2(*(const __half2*)&uyr.y);
            h4.x = fmaxf(acc.x * inv + ya.x + bb.x, 0.f);
            h4.y = fmaxf(acc.y * inv + ya.y + bb.y, 0.f);
            h4.z = fmaxf(acc.z * inv + yb.x + bb.z, 0.f);
            h4.w = fmaxf(acc.w * inv + yb.y + bb.w, 0.f);
        }
        __half2 h0 = __floats2half2_rn(h4.x, h4.y);
        __half2 h1 = __floats2half2_rn(h4.z, h4.w);
        *(uint2*)(AH + nl * TS + lane * 4) = make_uint2(*(uint32_t*)&h0, *(uint32_t*)&h1);
    }
    __syncthreads();

    // ---- Phase B: wmma gemm2 (single-pass fp16) ----
    int rblk = wid & 7;                 // rows rblk*16 .. +15
    int j0   = (wid < 8) ? 0 : 3;       // col frags {0,1,2} or {3,4}
    int nj   = (wid < 8) ? 3 : 2;

    wmma::fragment<wmma::accumulator, 16, 16, 16, float> C[3];
#pragma unroll
    for (int j = 0; j < 3; j++) wmma::fill_fragment(C[j], 0.0f);

#pragma unroll
    for (int k0 = 0; k0 < 8; k0++) {
        wmma::fragment<wmma::matrix_a, 16, 16, 16, __half, wmma::row_major> ah;
        wmma::load_matrix_sync(ah, AH + (rblk * 16) * TS + k0 * 16, TS);
        for (int j = 0; j < nj; j++) {
            wmma::fragment<wmma::matrix_b, 16, 16, 16, __half, wmma::row_major> bh;
            wmma::load_matrix_sync(bh, W2H + (k0 * 16) * T2S + (j0 + j) * 16, T2S);
            wmma::mma_sync(C[j], ah, bh, C[j]);
        }
    }
    __syncthreads();   // AH/W2H reads done -> reuse as fp32 staging

    // ---- epilogue: stage fp32 pq (128x80) in smem, convert to fp16 ----
    float* stage = (float*)sm;          // 40960B <= 55296B smem
    for (int j = 0; j < nj; j++)
        wmma::store_matrix_sync(stage + (rblk * 16) * 80 + (j0 + j) * 16, C[j],
                                80, wmma::mem_row_major);
    __syncthreads();
    for (int g = tid; g < 5120; g += 512) {   // 128 rows x 40 half2
        int row = g / 40, c2 = g % 40;
        float2 v = ((const float2*)stage)[g];
        __half2 hv = __floats2half2_rn(v.x, v.y);
        *(__half2*)(g_pqh + (size_t)(node0 + row) * 80 + c2 * 2) = hv;
    }
}

// ---------- layer-2 aggregation + bias + log_softmax ----------
// warp per node; 3 lane-groups of 10 gather 3 edges per load instruction.

__global__ void k_final(const float* __restrict__ b2, float* __restrict__ out) {
    int warp = (blockIdx.x * blockDim.x + threadIdx.x) >> 5;
    if (warp >= N_NODES) return;
    int lane = threadIdx.x & 31;
    int g  = lane / 10;          // 0,1,2 (lanes 30,31 idle)
    int gl = lane % 10;
    bool active = lane < 30;
    int rs = g_rowstart[warp], re = g_rowstart[warp + 1];
    float acc[4] = {0.f, 0.f, 0.f, 0.f};

    for (int i0 = rs; i0 < re; i0 += 32) {
        int nv = min(32, re - i0);
        int s = (lane < nv) ? g_csrc[i0 + lane] : 0;
        for (int j = 0; j < nv; j += 6) {
            int e0 = j + g, e1 = j + 3 + g;
            int src0 = __shfl_sync(0xffffffffu, s, (e0 < nv) ? e0 : 0);
            int src1 = __shfl_sync(0xffffffffu, s, (e1 < nv) ? e1 : 0);
            bool v0 = active && (e0 < nv);
            bool v1 = active && (e1 < nv);
            uint2 u0 = v0 ? *(const uint2*)(g_pqh + (size_t)src0 * 80 + gl * 4)
                          : make_uint2(0u, 0u);
            uint2 u1 = v1 ? *(const uint2*)(g_pqh + (size_t)src1 * 80 + gl * 4)
                          : make_uint2(0u, 0u);
            float2 a0 = __half22float2(*(const __half2*)&u0.x);
            float2 b0 = __half22float2(*(const __half2*)&u0.y);
            float2 a1 = __half22float2(*(const __half2*)&u1.x);
            float2 b1 = __half22float2(*(const __half2*)&u1.y);
            acc[0] += a0.x + a1.x;
            acc[1] += a0.y + a1.y;
            acc[2] += b0.x + b1.x;
            acc[3] += b0.y + b1.y;
        }
    }

    // combine the 3 lane groups: lane<10 pulls from lane+10, lane+20
#pragma unroll
    for (int k = 0; k < 4; k++) {
        float t1 = __shfl_sync(0xffffffffu, acc[k], (lane + 10) & 31);
        float t2 = __shfl_sync(0xffffffffu, acc[k], (lane + 20) & 31);
        acc[k] += t1 + t2;           // valid for lane < 10
    }

    float inv = 1.0f / fmaxf((float)(re - rs), 1.0f);
    float v0f, v1f, v2f, v3f;
    if (lane < 10) {
        uint2 uq = *(const uint2*)(g_pqh + (size_t)warp * 80 + 40 + gl * 4);
        float2 qa = __half22float2(*(const __half2*)&uq.x);
        float2 qb = __half22float2(*(const __half2*)&uq.y);
        float4 bbv = *(const float4*)(b2 + gl * 4);
        v0f = acc[0] * inv + bbv.x + qa.x;
        v1f = acc[1] * inv + bbv.y + qa.y;
        v2f = acc[2] * inv + bbv.z + qb.x;
        v3f = acc[3] * inv + bbv.w + qb.y;
    } else {
        v0f = v1f = v2f = v3f = -INFINITY;
    }

    float mx = fmaxf(fmaxf(v0f, v1f), fmaxf(v2f, v3f));
#pragma unroll
    for (int o = 16; o; o >>= 1) mx = fmaxf(mx, __shfl_xor_sync(0xffffffffu, mx, o));
    float se = 0.f;
    if (lane < 10)
        se = expf(v0f - mx) + expf(v1f - mx) + expf(v2f - mx) + expf(v3f - mx);
#pragma unroll
    for (int o = 16; o; o >>= 1) se += __shfl_xor_sync(0xffffffffu, se, o);
    float lse = logf(se);

    if (lane < 10) {
        float4 o4 = make_float4(v0f - mx - lse, v1f - mx - lse,
                                v2f - mx - lse, v3f - mx - lse);
        *(float4*)(out + (size_t)warp * 40 + gl * 4) = o4;
    }
}

// -------------------- launch --------------------

extern "C" void kernel_launch(void* const* d_in, const int* in_sizes, int n_in,
                              void* d_out, int out_size) {
    const float* x       = (const float*)d_in[0];
    const void*  ei      = d_in[1];
    const float* Wl1     = (const float*)d_in[2];
    const float* b1      = (const float*)d_in[3];
    const float* Wr1     = (const float*)d_in[4];
    const float* Wl2     = (const float*)d_in[5];
    const float* b2      = (const float*)d_in[6];
    const float* Wr2     = (const float*)d_in[7];
    float* out           = (float*)d_out;

    cudaFuncSetAttribute(k_gemm1, cudaFuncAttributeMaxDynamicSharedMemorySize, GEMM1_SMEM);
    cudaFuncSetAttribute(k_aggr_gemm2, cudaFuncAttributeMaxDynamicSharedMemorySize, FUSED_SMEM);

    // side stream + fork/join events (created once; deterministic work per call)
    static cudaStream_t s2 = nullptr;
    static cudaEvent_t ev_fork = nullptr, ev_join = nullptr;
    if (!s2) {
        cudaStreamCreateWithFlags(&s2, cudaStreamNonBlocking);
        cudaEventCreateWithFlags(&ev_fork, cudaEventDisableTiming);
        cudaEventCreateWithFlags(&ev_join, cudaEventDisableTiming);
    }

    k_prep_w<<<1, 1024>>>(Wl1, Wr1, Wl2, Wr2);

    // fork: gemm1 depends only on x + prep_w — run it alongside the CSR build
    cudaEventRecord(ev_fork, 0);
    cudaStreamWaitEvent(s2, ev_fork, 0);
    k_gemm1<<<148, 512, GEMM1_SMEM, s2>>>(x);
    cudaEventRecord(ev_join, s2);

    // main stream: CSR build chain (zero2 also does the dtype detect)
    k_zero2<<<(N_NODES + 255) / 256, 256>>>((const int*)ei);
    k_count<<<1024, 256>>>(ei);
    k_scan1<<<NB_SCAN, 1024>>>();
    k_scan2<<<1, 128>>>();
    k_scan3<<<NB_SCAN, 1024>>>();
    k_fill<<<1024, 256>>>(ei);

    // join: fused aggregation+gemm2 needs both CSR and y1/yr
    cudaStreamWaitEvent(0, ev_join, 0);
    k_aggr_gemm2<<<N_PAD / 128, 512, FUSED_SMEM>>>(b1);
    k_final<<<(N_NODES * 32 + 255) / 256, 256>>>(b2, out);
}